// round 12
// baseline (speedup 1.0000x reference)
#include <cuda_runtime.h>
#include <cuda_fp16.h>
#include <math.h>
#include <stdint.h>

#define NP 50000
#define ND 5000
#define FD 512

// ---------------------------------------------------------------------------
// Scratch (u32 units)
// ---------------------------------------------------------------------------
constexpr size_t NPF   = (size_t)NP * FD;
constexpr size_t NDF   = (size_t)ND * FD;
constexpr size_t U_SUM_PP = 0;
constexpr size_t U_SUM_DP = U_SUM_PP + NPF;
constexpr size_t U_SUM_PD = U_SUM_DP + NPF;
constexpr size_t U_CNT_PP = U_SUM_PD + NDF;
constexpr size_t U_CNT_DP = U_CNT_PP + NP;
constexpr size_t U_CNT_PD = U_CNT_DP + NP;
constexpr size_t ZERO_END = U_CNT_PD + ND;
constexpr size_t U_XH_P   = (ZERO_END + 1) & ~(size_t)1;  // half x (plain)
constexpr size_t U_XH_D   = U_XH_P + NPF / 2;
constexpr size_t U_XNH_P  = U_XH_D + NDF / 2;             // half x (normalized)
constexpr size_t U_XNH_D  = U_XNH_P + NPF / 2;
constexpr size_t U_RECH_P = U_XNH_D + NDF / 2;            // half rec (normalized)
constexpr size_t U_RECH_D = U_RECH_P + NPF / 2;
constexpr size_t U_WCOMB  = U_RECH_D + NDF / 2;
constexpr size_t U_WRPP   = U_WCOMB + (size_t)FD * FD / 2;
constexpr size_t U_WRDP   = U_WRPP + (size_t)FD * FD / 2;
constexpr size_t U_WRPD   = U_WRDP + (size_t)FD * FD / 2;
constexpr size_t U_WLPD   = U_WRPD + (size_t)FD * FD / 2;
constexpr size_t U_WDECP  = U_WLPD + (size_t)FD * FD / 2;
constexpr size_t U_WDECD  = U_WDECP + (size_t)FD * FD;
constexpr size_t U_BSUM   = U_WDECD + (size_t)FD * FD;
constexpr size_t U_TOTAL  = U_BSUM + FD;

__device__ __align__(16) unsigned g_scratch[U_TOTAL];

__device__ __forceinline__ unsigned pack_h2(float a, float b) {
    __half2 h = __floats2half2_rn(a, b);
    return *reinterpret_cast<unsigned*>(&h);
}

// ---------------------------------------------------------------------------
// k1: zero + weight prep + x -> half (plain + normalized), phased grid
// ---------------------------------------------------------------------------
struct PrepArgs {
    const float *wlpp, *wldp, *wrpp, *wrdp, *wrpd, *wlpd, *wdecp, *wdecd, *bpp, *bdp;
    unsigned *o_wcomb, *o_wrpp, *o_wrdp, *o_wrpd, *o_wlpd, *o_wdecp, *o_wdecd;
    float* o_bsum;
    const float* xin[2];
    uint2* xout_p[2];
    uint2* xout_n[2];
    int xrows[2];
    float4* zbase;
    size_t zn4;
    unsigned nW, nX;
};

__global__ void zero_prep(PrepArgs a) {
    if (blockIdx.x < a.nW) {
        size_t idx = (size_t)blockIdx.x * blockDim.x + threadIdx.x;
        const int nh = FD * FD / 2;
        if (idx < (size_t)nh) {
            int j = 2 * (int)idx;
            a.o_wcomb[idx] = pack_h2(a.wlpp[j] + a.wldp[j], a.wlpp[j + 1] + a.wldp[j + 1]);
            a.o_wrpp[idx]  = pack_h2(a.wrpp[j], a.wrpp[j + 1]);
            a.o_wrdp[idx]  = pack_h2(a.wrdp[j], a.wrdp[j + 1]);
            a.o_wrpd[idx]  = pack_h2(a.wrpd[j], a.wrpd[j + 1]);
            a.o_wlpd[idx]  = pack_h2(a.wlpd[j], a.wlpd[j + 1]);
        }
        if (idx < (size_t)(2 * nh)) {
            int j = 2 * (int)idx;
            a.o_wdecp[idx] = pack_h2(a.wdecp[j], a.wdecp[j + 1]);
            a.o_wdecd[idx] = pack_h2(a.wdecd[j], a.wdecd[j + 1]);
        }
        if (idx < FD) a.o_bsum[idx] = a.bpp[idx] + a.bdp[idx];
        return;
    }
    if (blockIdx.x < a.nW + a.nX) {
        int row = (int)((((size_t)(blockIdx.x - a.nW) * blockDim.x) + threadIdx.x) >> 5);
        int t = 0;
        if (row >= a.xrows[0]) { row -= a.xrows[0]; t = 1; }
        if (t == 1 && row >= a.xrows[1]) return;
        int lane = threadIdx.x & 31;
        const float4* p = (const float4*)(a.xin[t] + (size_t)row * FD);
        float4 v[4];
        float ss = 0.f;
#pragma unroll
        for (int i = 0; i < 4; i++) {
            v[i] = p[lane + 32 * i];
            ss += v[i].x * v[i].x + v[i].y * v[i].y + v[i].z * v[i].z + v[i].w * v[i].w;
        }
#pragma unroll
        for (int o = 16; o > 0; o >>= 1) ss += __shfl_xor_sync(0xffffffffu, ss, o);
        float inv = 1.0f / fmaxf(sqrtf(ss), 1e-12f);
        uint2* qp = a.xout_p[t] + (size_t)row * 128;
        uint2* qn = a.xout_n[t] + (size_t)row * 128;
#pragma unroll
        for (int i = 0; i < 4; i++) {
            qp[lane + 32 * i] = make_uint2(pack_h2(v[i].x, v[i].y),
                                           pack_h2(v[i].z, v[i].w));
            qn[lane + 32 * i] = make_uint2(pack_h2(v[i].x * inv, v[i].y * inv),
                                           pack_h2(v[i].z * inv, v[i].w * inv));
        }
        return;
    }
    size_t i = (size_t)(blockIdx.x - a.nW - a.nX) * blockDim.x + threadIdx.x;
    size_t stride = (size_t)(gridDim.x - a.nW - a.nX) * blockDim.x;
    for (; i < a.zn4; i += stride)
        a.zbase[i] = make_float4(0.f, 0.f, 0.f, 0.f);
}

// ---------------------------------------------------------------------------
// k2: scatter — gather half x, fp32 red. 64 lanes/edge, 4 edges/block.
// ---------------------------------------------------------------------------
struct ScatArgs {
    const int* ei[3];
    const __half* x[3];
    float* sum[3];
    float* cnt[3];
    int E[3];
    int b0, b01;
};

__global__ void scatter_all(ScatArgs a) {
    int b = blockIdx.x, t;
    if (b < a.b0)       { t = 0; }
    else if (b < a.b01) { t = 1; b -= a.b0; }
    else                { t = 2; b -= a.b01; }
    int e = b * 4 + (threadIdx.x >> 6);
    if (e >= a.E[t]) return;
    int lane = threadIdx.x & 63;
    int src = a.ei[t][e];
    int dst = a.ei[t][(size_t)a.E[t] + e];
    uint4 hv = *(const uint4*)(a.x[t] + (size_t)src * FD + lane * 8);
    float2 f0 = __half22float2(*(__half2*)&hv.x);
    float2 f1 = __half22float2(*(__half2*)&hv.y);
    float2 f2 = __half22float2(*(__half2*)&hv.z);
    float2 f3 = __half22float2(*(__half2*)&hv.w);
    float* o = a.sum[t] + (size_t)dst * FD + lane * 8;
    asm volatile("red.global.add.v4.f32 [%0], {%1,%2,%3,%4};"
                 :: "l"(o), "f"(f0.x), "f"(f0.y), "f"(f1.x), "f"(f1.y) : "memory");
    asm volatile("red.global.add.v4.f32 [%0], {%1,%2,%3,%4};"
                 :: "l"(o + 4), "f"(f2.x), "f"(f2.y), "f"(f3.x), "f"(f3.y) : "memory");
    if (lane == 0) atomicAdd(a.cnt[t] + dst, 1.0f);
}

// ---------------------------------------------------------------------------
// shared GEMM helpers
// ---------------------------------------------------------------------------
#define SROW_H 40

__device__ __forceinline__ void cp16s(uint32_t dst_smem, const void* src) {
    asm volatile("cp.async.cg.shared.global [%0], [%1], 16;"
                 :: "r"(dst_smem), "l"(src));
}
__device__ __forceinline__ uint32_t smem_u32(const void* p) {
    uint32_t a;
    asm("{ .reg .u64 t; cvta.to.shared.u64 t, %1; cvt.u32.u64 %0, t; }"
        : "=r"(a) : "l"(p));
    return a;
}
#define LDMX4(r0, r1, r2, r3, addr) \
    asm volatile("ldmatrix.sync.aligned.m8n8.x4.shared.b16 {%0,%1,%2,%3}, [%4];" \
                 : "=r"(r0), "=r"(r1), "=r"(r2), "=r"(r3) : "r"(addr))
#define MMA16816(acc, av, bv) \
    asm volatile( \
        "mma.sync.aligned.m16n8k16.row.col.f32.f16.f16.f32 " \
        "{%0,%1,%2,%3}, {%4,%5,%6,%7}, {%8,%9}, {%0,%1,%2,%3};" \
        : "+f"((acc)[0]), "+f"((acc)[1]), "+f"((acc)[2]), "+f"((acc)[3]) \
        : "r"((av)[0]), "r"((av)[1]), "r"((av)[2]), "r"((av)[3]), \
          "r"((bv)[0]), "r"((bv)[1]))

extern __shared__ __align__(128) unsigned char hsm[];

// ---------------------------------------------------------------------------
// Encoder GEMM: BM=64 x BN=512(full) x BK=32, 256 thr / 8 warps (1x8),
// warp tile 64x64. A staged via LDG(fp32 or half) -> scale -> half -> STS,
// register double-buffered one chunk ahead; B via 4-stage cp.async.
// Epilogue: +bias, full-row L2 norm, write half normalized.
// ---------------------------------------------------------------------------
struct SegE {
    const void* A;        // fp32 (with cnt) or half
    const float* cnt;     // row counts (scale = 1/max(cnt,1)) or null
    int isHalf;
    const __half* B;
    int ldb;
};
struct ProbE {
    SegE seg[3];
    int nseg;
    const float* bias;
    __half* Ch;
    int M;
};

#define E_ASTG (64 * SROW_H * 2)          // 5120
#define E_BSTG (512 * SROW_H * 2)         // 40960
#define E_STG  (E_ASTG + E_BSTG)          // 46080
#define E_SMEM (4 * E_STG)                // 184320

__global__ __launch_bounds__(256, 1) void gemm_enc(ProbE p0, ProbE p1, int split) {
    const bool first = (blockIdx.x < (unsigned)split);
    ProbE p = first ? p0 : p1;
    const int bm = (first ? blockIdx.x : blockIdx.x - split) * 64;

    const int tid  = threadIdx.x;
    const int lane = tid & 31;
    const int wn   = tid >> 5;           // 0..7
    const int g    = lane >> 2;
    const int t4   = lane & 3;

    const uint32_t dyn = smem_u32(hsm);
    __shared__ float rowss[64];

    const uint32_t aoff =
        (uint32_t)(((lane & 15) * SROW_H + ((lane >> 4) << 3)) * 2);
    const uint32_t boff = E_ASTG +
        (uint32_t)(((wn * 64 + (lane & 7) + (((lane >> 4) & 1) << 3)) * SROW_H +
                    (((lane >> 3) & 1) << 3)) * 2);

    float acc[4][8][4];
#pragma unroll
    for (int mi = 0; mi < 4; mi++)
#pragma unroll
        for (int ni = 0; ni < 8; ni++)
#pragma unroll
            for (int r = 0; r < 4; r++) acc[mi][ni][r] = 0.f;

    const int NKB = p.nseg * (FD / 32);

    // this thread's A row/col while staging
    const int arow = tid >> 2;           // 0..63
    const int agr  = bm + arow;
    const bool aok = agr < p.M;
    const int ac8  = (tid & 3) * 8;      // element offset (8 elems = 16B half)
    unsigned RA[4];

    auto issueB = [&](int kb) {
        const int st   = kb & 3;
        const int s    = kb >> 4;
        const int koff = (kb & 15) * 32;
        const __half* Bb = p.seg[s].B;
        const int ldb = p.seg[s].ldb;
        const uint32_t bbase = dyn + st * E_STG + E_ASTG;
#pragma unroll
        for (int i = 0; i < 8; i++) {    // B: 2048 x 16B jobs
            int u = tid + i * 256;
            int row = u >> 2, c16 = u & 3;
            cp16s(bbase + (uint32_t)(row * (SROW_H * 2) + c16 * 16),
                  Bb + (size_t)row * ldb + koff + c16 * 8);
        }
        asm volatile("cp.async.commit_group;");
    };

    auto ldA = [&](int kb) {
        const int s    = kb >> 4;
        const int koff = (kb & 15) * 32;
        if (!aok) { RA[0] = RA[1] = RA[2] = RA[3] = 0; return; }
        if (p.seg[s].isHalf) {
            uint4 v = *(const uint4*)((const __half*)p.seg[s].A +
                                      (size_t)agr * FD + koff + ac8);
            RA[0] = v.x; RA[1] = v.y; RA[2] = v.z; RA[3] = v.w;
        } else {
            const float* Af = (const float*)p.seg[s].A +
                              (size_t)agr * FD + koff + ac8;
            float sc = p.seg[s].cnt ? 1.0f / fmaxf(p.seg[s].cnt[agr], 1.0f) : 1.0f;
            float4 a = *(const float4*)Af;
            float4 b = *(const float4*)(Af + 4);
            RA[0] = pack_h2(a.x * sc, a.y * sc);
            RA[1] = pack_h2(a.z * sc, a.w * sc);
            RA[2] = pack_h2(b.x * sc, b.y * sc);
            RA[3] = pack_h2(b.z * sc, b.w * sc);
        }
    };

    auto stA = [&](int kb) {
        const int st = kb & 3;
        uint32_t dst = dyn + st * E_STG + (uint32_t)(arow * (SROW_H * 2) + (tid & 3) * 16);
        asm volatile("st.shared.v4.u32 [%0], {%1,%2,%3,%4};"
                     :: "r"(dst), "r"(RA[0]), "r"(RA[1]), "r"(RA[2]), "r"(RA[3]));
    };

    issueB(0);
    if (NKB > 1) issueB(1);
    if (NKB > 2) issueB(2);
    ldA(0); stA(0);
    if (NKB > 1) ldA(1);

    for (int c = 0; c < NKB; c++) {
        const int st = c & 3;
        const int rem = NKB - 1 - c;
        if (rem >= 3)      asm volatile("cp.async.wait_group 3;");
        else if (rem == 2) asm volatile("cp.async.wait_group 2;");
        else if (rem == 1) asm volatile("cp.async.wait_group 1;");
        else               asm volatile("cp.async.wait_group 0;");
        __syncthreads();

        const uint32_t stBase = dyn + st * E_STG;
#pragma unroll
        for (int ks = 0; ks < 2; ks++) {
            unsigned a[4][4], b[8][2];
#pragma unroll
            for (int mi = 0; mi < 4; mi++)
                LDMX4(a[mi][0], a[mi][1], a[mi][2], a[mi][3],
                      stBase + aoff + (uint32_t)(mi * 16 * SROW_H * 2 + ks * 32));
#pragma unroll
            for (int pi = 0; pi < 4; pi++)
                LDMX4(b[2 * pi][0], b[2 * pi][1], b[2 * pi + 1][0], b[2 * pi + 1][1],
                      stBase + boff + (uint32_t)(pi * 16 * SROW_H * 2 + ks * 32));
#pragma unroll
            for (int mi = 0; mi < 4; mi++)
#pragma unroll
                for (int ni = 0; ni < 8; ni++)
                    MMA16816(acc[mi][ni], a[mi], b[ni]);
        }
        __syncthreads();

        if (c + 3 < NKB) issueB(c + 3);
        if (c + 1 < NKB) stA(c + 1);
        if (c + 2 < NKB) ldA(c + 2);
    }

    // epilogue: +bias, row ssq over full 512 cols, normalize, write half
    float bb[8][2];
#pragma unroll
    for (int ni = 0; ni < 8; ni++) {
        int c = wn * 64 + ni * 8 + t4 * 2;
        bb[ni][0] = p.bias[c];
        bb[ni][1] = p.bias[c + 1];
    }
    if (tid < 64) rowss[tid] = 0.f;
    __syncthreads();
#pragma unroll
    for (int mi = 0; mi < 4; mi++) {
        float s0 = 0.f, s1 = 0.f;
#pragma unroll
        for (int ni = 0; ni < 8; ni++) {
            float v0 = acc[mi][ni][0] + bb[ni][0];
            float v1 = acc[mi][ni][1] + bb[ni][1];
            float v2 = acc[mi][ni][2] + bb[ni][0];
            float v3 = acc[mi][ni][3] + bb[ni][1];
            acc[mi][ni][0] = v0; acc[mi][ni][1] = v1;
            acc[mi][ni][2] = v2; acc[mi][ni][3] = v3;
            s0 += v0 * v0 + v1 * v1;
            s1 += v2 * v2 + v3 * v3;
        }
        s0 += __shfl_xor_sync(0xffffffffu, s0, 1);
        s0 += __shfl_xor_sync(0xffffffffu, s0, 2);
        s1 += __shfl_xor_sync(0xffffffffu, s1, 1);
        s1 += __shfl_xor_sync(0xffffffffu, s1, 2);
        if (t4 == 0) {
            atomicAdd(&rowss[mi * 16 + g], s0);
            atomicAdd(&rowss[mi * 16 + g + 8], s1);
        }
    }
    __syncthreads();
#pragma unroll
    for (int mi = 0; mi < 4; mi++) {
        const int r0 = mi * 16 + g;
        const int gr0 = bm + r0;
        const float inv0 = 1.0f / fmaxf(sqrtf(rowss[r0]), 1e-12f);
        const float inv1 = 1.0f / fmaxf(sqrtf(rowss[r0 + 8]), 1e-12f);
#pragma unroll
        for (int ni = 0; ni < 8; ni++) {
            const int c = wn * 64 + ni * 8 + t4 * 2;
            if (gr0 < p.M)
                *(unsigned*)(p.Ch + (size_t)gr0 * FD + c) =
                    pack_h2(acc[mi][ni][0] * inv0, acc[mi][ni][1] * inv0);
            if (gr0 + 8 < p.M)
                *(unsigned*)(p.Ch + (size_t)(gr0 + 8) * FD + c) =
                    pack_h2(acc[mi][ni][2] * inv1, acc[mi][ni][3] * inv1);
        }
    }
}

// ---------------------------------------------------------------------------
// Decoder GEMM (R10 config): 128x256x32, 512 thr / 16 warps, warp 64x32.
// ---------------------------------------------------------------------------
struct SegH {
    const __half* A[3];
    const __half* B[3];
    int ldb[3];
};
struct ProbH {
    SegH segs;
    int nseg;
    const float* bias;
    float* C;
    int M;
};

#define NTHR 512
#define A_BYTES_H (128 * SROW_H * 2)
#define B_BYTES_H (256 * SROW_H * 2)
#define STG_H (A_BYTES_H + B_BYTES_H)
#define GEMM_SMEM (4 * STG_H)

__global__ __launch_bounds__(NTHR, 1) void gemm_h(ProbH p0, ProbH p1, int split) {
    const bool first = (blockIdx.x < (unsigned)split);
    ProbH p = first ? p0 : p1;
    const int bm = (first ? blockIdx.x : blockIdx.x - split) * 128;
    const int bn = blockIdx.y * 256;

    const int tid  = threadIdx.x;
    const int lane = tid & 31;
    const int warp = tid >> 5;
    const int wm = warp >> 3;
    const int wn = warp & 7;
    const int g  = lane >> 2;
    const int t4 = lane & 3;

    const uint32_t dyn = smem_u32(hsm);

    const uint32_t aoff =
        (uint32_t)(((wm * 64 + (lane & 15)) * SROW_H + ((lane >> 4) << 3)) * 2);
    const uint32_t boff = A_BYTES_H +
        (uint32_t)(((wn * 32 + (lane & 7) + (((lane >> 4) & 1) << 3)) * SROW_H +
                    (((lane >> 3) & 1) << 3)) * 2);

    float acc[4][4][4];
#pragma unroll
    for (int mi = 0; mi < 4; mi++)
#pragma unroll
        for (int ni = 0; ni < 4; ni++)
#pragma unroll
            for (int r = 0; r < 4; r++) acc[mi][ni][r] = 0.f;

    const int NKB = p.nseg * (FD / 32);

    auto issue = [&](int kb) {
        const int st   = kb & 3;
        const int s    = kb >> 4;
        const int koff = (kb & 15) * 32;
        const uint32_t abase = dyn + st * STG_H;
        const uint32_t bbase = abase + A_BYTES_H;
        {
            int row = tid >> 2, c16 = tid & 3;
            int r = bm + row;
            if (r < p.M)
                cp16s(abase + (uint32_t)(row * (SROW_H * 2) + c16 * 16),
                      p.segs.A[s] + (size_t)r * FD + koff + c16 * 8);
            else {
                uint32_t d = abase + (uint32_t)(row * (SROW_H * 2) + c16 * 16);
                asm volatile("st.shared.v4.u32 [%0], {%1,%1,%1,%1};"
                             :: "r"(d), "r"(0u));
            }
        }
        const __half* Bb = p.segs.B[s];
        const int ldb = p.segs.ldb[s];
#pragma unroll
        for (int i = 0; i < 2; i++) {
            int u = tid + i * NTHR;
            int row = u >> 2, c16 = u & 3;
            cp16s(bbase + (uint32_t)(row * (SROW_H * 2) + c16 * 16),
                  Bb + (size_t)(bn + row) * ldb + koff + c16 * 8);
        }
        asm volatile("cp.async.commit_group;");
    };

    issue(0);
    if (NKB > 1) issue(1);
    if (NKB > 2) issue(2);

    for (int c = 0; c < NKB; c++) {
        const int st = c & 3;
        if (c + 3 < NKB) issue(c + 3);
        const int rem = NKB - 1 - c;
        if (rem >= 3)      asm volatile("cp.async.wait_group 3;");
        else if (rem == 2) asm volatile("cp.async.wait_group 2;");
        else if (rem == 1) asm volatile("cp.async.wait_group 1;");
        else               asm volatile("cp.async.wait_group 0;");
        __syncthreads();

        const uint32_t stBase = dyn + st * STG_H;
#pragma unroll
        for (int ks = 0; ks < 2; ks++) {
            unsigned a[4][4], b[4][2];
#pragma unroll
            for (int mi = 0; mi < 4; mi++)
                LDMX4(a[mi][0], a[mi][1], a[mi][2], a[mi][3],
                      stBase + aoff + (uint32_t)(mi * 16 * SROW_H * 2 + ks * 32));
#pragma unroll
            for (int pi = 0; pi < 2; pi++)
                LDMX4(b[2 * pi][0], b[2 * pi][1], b[2 * pi + 1][0], b[2 * pi + 1][1],
                      stBase + boff + (uint32_t)(pi * 16 * SROW_H * 2 + ks * 32));
#pragma unroll
            for (int mi = 0; mi < 4; mi++)
#pragma unroll
                for (int ni = 0; ni < 4; ni++)
                    MMA16816(acc[mi][ni], a[mi], b[ni]);
        }
        __syncthreads();
    }

#pragma unroll
    for (int ni = 0; ni < 4; ni++) {
        const int c = bn + wn * 32 + ni * 8 + t4 * 2;
        const float bb0 = p.bias[c];
        const float bb1 = p.bias[c + 1];
#pragma unroll
        for (int mi = 0; mi < 4; mi++) {
            const int r0 = bm + wm * 64 + mi * 16 + g;
            if (r0 < p.M)
                *(float2*)(p.C + (size_t)r0 * FD + c) =
                    make_float2(acc[mi][ni][0] + bb0, acc[mi][ni][1] + bb1);
            const int r1 = r0 + 8;
            if (r1 < p.M)
                *(float2*)(p.C + (size_t)r1 * FD + c) =
                    make_float2(acc[mi][ni][2] + bb0, acc[mi][ni][3] + bb1);
        }
    }
}

// ---------------------------------------------------------------------------
// kernel_launch — 4 launches
// ---------------------------------------------------------------------------
extern "C" void kernel_launch(void* const* d_in, const int* in_sizes, int n_in,
                              void* d_out, int out_size) {
    const float* x_paper   = (const float*)d_in[0];
    const float* x_dataset = (const float*)d_in[1];
    const int*   ei_pp     = (const int*)d_in[2];
    const int*   ei_pd     = (const int*)d_in[3];
    const int*   ei_dp     = (const int*)d_in[4];
    const float* Wl_pp = (const float*)d_in[5];
    const float* Wr_pp = (const float*)d_in[6];
    const float* b_pp  = (const float*)d_in[7];
    const float* Wl_pd = (const float*)d_in[8];
    const float* Wr_pd = (const float*)d_in[9];
    const float* b_pd  = (const float*)d_in[10];
    const float* Wl_dp = (const float*)d_in[11];
    const float* Wr_dp = (const float*)d_in[12];
    const float* b_dp  = (const float*)d_in[13];
    const float* Wdec_p = (const float*)d_in[14];
    const float* bdec_p = (const float*)d_in[15];
    const float* Wdec_d = (const float*)d_in[16];
    const float* bdec_d = (const float*)d_in[17];

    const int Epp = in_sizes[2] / 2;
    const int Epd = in_sizes[3] / 2;
    const int Edp = in_sizes[4] / 2;

    float* out = (float*)d_out;

    unsigned* base = nullptr;
    cudaGetSymbolAddress((void**)&base, g_scratch);
    float*    sum_pp = (float*)(base + U_SUM_PP);
    float*    sum_dp = (float*)(base + U_SUM_DP);
    float*    sum_pd = (float*)(base + U_SUM_PD);
    float*    cnt_pp = (float*)(base + U_CNT_PP);
    float*    cnt_dp = (float*)(base + U_CNT_DP);
    float*    cnt_pd = (float*)(base + U_CNT_PD);
    __half*   xh_p   = (__half*)(base + U_XH_P);
    __half*   xh_d   = (__half*)(base + U_XH_D);
    __half*   xnh_p  = (__half*)(base + U_XNH_P);
    __half*   xnh_d  = (__half*)(base + U_XNH_D);
    __half*   rech_p = (__half*)(base + U_RECH_P);
    __half*   rech_d = (__half*)(base + U_RECH_D);
    __half*   wcomb  = (__half*)(base + U_WCOMB);
    __half*   wrpp   = (__half*)(base + U_WRPP);
    __half*   wrdp   = (__half*)(base + U_WRDP);
    __half*   wrpd   = (__half*)(base + U_WRPD);
    __half*   wlpd   = (__half*)(base + U_WLPD);
    __half*   wdecp  = (__half*)(base + U_WDECP);
    __half*   wdecd  = (__half*)(base + U_WDECD);
    float*    bsum   = (float*)(base + U_BSUM);

    cudaFuncSetAttribute(gemm_enc, cudaFuncAttributeMaxDynamicSharedMemorySize,
                         E_SMEM);
    cudaFuncSetAttribute(gemm_h, cudaFuncAttributeMaxDynamicSharedMemorySize,
                         GEMM_SMEM);

    // k1: zero + weight prep + x -> half (plain + normalized)
    PrepArgs pa;
    pa.wlpp = Wl_pp; pa.wldp = Wl_dp; pa.wrpp = Wr_pp; pa.wrdp = Wr_dp;
    pa.wrpd = Wr_pd; pa.wlpd = Wl_pd; pa.wdecp = Wdec_p; pa.wdecd = Wdec_d;
    pa.bpp = b_pp; pa.bdp = b_dp;
    pa.o_wcomb = (unsigned*)wcomb; pa.o_wrpp = (unsigned*)wrpp;
    pa.o_wrdp = (unsigned*)wrdp; pa.o_wrpd = (unsigned*)wrpd;
    pa.o_wlpd = (unsigned*)wlpd; pa.o_wdecp = (unsigned*)wdecp;
    pa.o_wdecd = (unsigned*)wdecd; pa.o_bsum = bsum;
    pa.xin[0] = x_paper;   pa.xout_p[0] = (uint2*)xh_p; pa.xout_n[0] = (uint2*)xnh_p; pa.xrows[0] = NP;
    pa.xin[1] = x_dataset; pa.xout_p[1] = (uint2*)xh_d; pa.xout_n[1] = (uint2*)xnh_d; pa.xrows[1] = ND;
    pa.zbase = (float4*)base; pa.zn4 = ZERO_END / 4;
    pa.nW = (unsigned)((FD * FD + 255) / 256);
    pa.nX = (unsigned)(((size_t)(NP + ND) * 32 + 255) / 256);
    zero_prep<<<pa.nW + pa.nX + 4096, 256>>>(pa);

    // k2: scatter (gathers half x)
    ScatArgs sa;
    sa.ei[0] = ei_pp; sa.x[0] = xh_p; sa.sum[0] = sum_pp; sa.cnt[0] = cnt_pp; sa.E[0] = Epp;
    sa.ei[1] = ei_dp; sa.x[1] = xh_d; sa.sum[1] = sum_dp; sa.cnt[1] = cnt_dp; sa.E[1] = Edp;
    sa.ei[2] = ei_pd; sa.x[2] = xh_p; sa.sum[2] = sum_pd; sa.cnt[2] = cnt_pd; sa.E[2] = Epd;
    int nb0 = (Epp + 3) / 4, nb1 = (Edp + 3) / 4, nb2 = (Epd + 3) / 4;
    sa.b0 = nb0; sa.b01 = nb0 + nb1;
    scatter_all<<<nb0 + nb1 + nb2, 256>>>(sa);

    // k3: encoder GEMMs, fused mean + convert (A path) and L2-norm epilogue
    const int gpe = (NP + 63) / 64;   // 782
    const int gde = (ND + 63) / 64;   // 79
    ProbE e0 = {}, e1 = {};
    e0.seg[0] = { sum_pp, cnt_pp, 0, wrpp,  FD };
    e0.seg[1] = { sum_dp, cnt_dp, 0, wrdp,  FD };
    e0.seg[2] = { xh_p,   nullptr, 1, wcomb, FD };
    e0.nseg = 3; e0.bias = bsum; e0.Ch = rech_p; e0.M = NP;
    e1.seg[0] = { sum_pd, cnt_pd, 0, wrpd, FD };
    e1.seg[1] = { xh_d,   nullptr, 1, wlpd, FD };
    e1.nseg = 2; e1.bias = b_pd; e1.Ch = rech_d; e1.M = ND;
    gemm_enc<<<gpe + gde, 256, E_SMEM>>>(e0, e1, gpe);

    // k4: decoder GEMMs -> out (fp32)
    const int gp = (NP + 127) / 128;
    const int gd = (ND + 127) / 128;
    dim3 ggrid(gp + gd, FD / 256);
    ProbH d0 = {}, d1 = {};
    d0.segs.A[0] = rech_p; d0.segs.B[0] = wdecp;      d0.segs.ldb[0] = 2 * FD;
    d0.segs.A[1] = xnh_p;  d0.segs.B[1] = wdecp + FD; d0.segs.ldb[1] = 2 * FD;
    d0.nseg = 2; d0.bias = bdec_p; d0.C = out; d0.M = NP;
    d1.segs.A[0] = rech_d; d1.segs.B[0] = wdecd;      d1.segs.ldb[0] = 2 * FD;
    d1.segs.A[1] = xnh_d;  d1.segs.B[1] = wdecd + FD; d1.segs.ldb[1] = 2 * FD;
    d1.nseg = 2; d1.bias = bdec_d; d1.C = out + (size_t)NP * FD; d1.M = ND;
    gemm_h<<<ggrid, NTHR, GEMM_SMEM>>>(d0, d1, gp);
}

// round 13
// speedup vs baseline: 1.0254x; 1.0254x over previous
#include <cuda_runtime.h>
#include <cuda_fp16.h>
#include <math.h>
#include <stdint.h>

#define NP 50000
#define ND 5000
#define FD 512

// ---------------------------------------------------------------------------
// Scratch (u32 units)
// ---------------------------------------------------------------------------
constexpr size_t NPF   = (size_t)NP * FD;
constexpr size_t NDF   = (size_t)ND * FD;
constexpr size_t U_SUM_PP = 0;
constexpr size_t U_SUM_DP = U_SUM_PP + NPF;
constexpr size_t U_SUM_PD = U_SUM_DP + NPF;
constexpr size_t U_CNT_PP = U_SUM_PD + NDF;
constexpr size_t U_CNT_DP = U_CNT_PP + NP;
constexpr size_t U_CNT_PD = U_CNT_DP + NP;
constexpr size_t ZERO_END = U_CNT_PD + ND;
constexpr size_t U_MH_PP  = (ZERO_END + 1) & ~(size_t)1;
constexpr size_t U_MH_DP  = U_MH_PP + NPF / 2;
constexpr size_t U_MH_PD  = U_MH_DP + NPF / 2;
constexpr size_t U_XH_P   = U_MH_PD + NDF / 2;     // half x (plain)
constexpr size_t U_XH_D   = U_XH_P + NPF / 2;
constexpr size_t U_XNH_P  = U_XH_D + NDF / 2;      // half x (normalized)
constexpr size_t U_XNH_D  = U_XNH_P + NPF / 2;
constexpr size_t U_RECH_P = U_XNH_D + NDF / 2;     // half rec (normalized)
constexpr size_t U_RECH_D = U_RECH_P + NPF / 2;
constexpr size_t U_WCOMB  = U_RECH_D + NDF / 2;
constexpr size_t U_WRPP   = U_WCOMB + (size_t)FD * FD / 2;
constexpr size_t U_WRDP   = U_WRPP + (size_t)FD * FD / 2;
constexpr size_t U_WRPD   = U_WRDP + (size_t)FD * FD / 2;
constexpr size_t U_WLPD   = U_WRPD + (size_t)FD * FD / 2;
constexpr size_t U_WDECP  = U_WLPD + (size_t)FD * FD / 2;
constexpr size_t U_WDECD  = U_WDECP + (size_t)FD * FD;
constexpr size_t U_BSUM   = U_WDECD + (size_t)FD * FD;
constexpr size_t U_TOTAL  = U_BSUM + FD;

__device__ __align__(16) unsigned g_scratch[U_TOTAL];

__device__ __forceinline__ unsigned pack_h2(float a, float b) {
    __half2 h = __floats2half2_rn(a, b);
    return *reinterpret_cast<unsigned*>(&h);
}

// ---------------------------------------------------------------------------
// k1: zero + weight prep + x -> half (plain + normalized), phased grid
// ---------------------------------------------------------------------------
struct PrepArgs {
    const float *wlpp, *wldp, *wrpp, *wrdp, *wrpd, *wlpd, *wdecp, *wdecd, *bpp, *bdp;
    unsigned *o_wcomb, *o_wrpp, *o_wrdp, *o_wrpd, *o_wlpd, *o_wdecp, *o_wdecd;
    float* o_bsum;
    const float* xin[2];
    uint2* xout_p[2];
    uint2* xout_n[2];
    int xrows[2];
    float4* zbase;
    size_t zn4;
    unsigned nW, nX;
};

__global__ void zero_prep(PrepArgs a) {
    if (blockIdx.x < a.nW) {
        size_t idx = (size_t)blockIdx.x * blockDim.x + threadIdx.x;
        const int nh = FD * FD / 2;
        if (idx < (size_t)nh) {
            int j = 2 * (int)idx;
            a.o_wcomb[idx] = pack_h2(a.wlpp[j] + a.wldp[j], a.wlpp[j + 1] + a.wldp[j + 1]);
            a.o_wrpp[idx]  = pack_h2(a.wrpp[j], a.wrpp[j + 1]);
            a.o_wrdp[idx]  = pack_h2(a.wrdp[j], a.wrdp[j + 1]);
            a.o_wrpd[idx]  = pack_h2(a.wrpd[j], a.wrpd[j + 1]);
            a.o_wlpd[idx]  = pack_h2(a.wlpd[j], a.wlpd[j + 1]);
        }
        if (idx < (size_t)(2 * nh)) {
            int j = 2 * (int)idx;
            a.o_wdecp[idx] = pack_h2(a.wdecp[j], a.wdecp[j + 1]);
            a.o_wdecd[idx] = pack_h2(a.wdecd[j], a.wdecd[j + 1]);
        }
        if (idx < FD) a.o_bsum[idx] = a.bpp[idx] + a.bdp[idx];
        return;
    }
    if (blockIdx.x < a.nW + a.nX) {
        int row = (int)((((size_t)(blockIdx.x - a.nW) * blockDim.x) + threadIdx.x) >> 5);
        int t = 0;
        if (row >= a.xrows[0]) { row -= a.xrows[0]; t = 1; }
        if (t == 1 && row >= a.xrows[1]) return;
        int lane = threadIdx.x & 31;
        const float4* p = (const float4*)(a.xin[t] + (size_t)row * FD);
        float4 v[4];
        float ss = 0.f;
#pragma unroll
        for (int i = 0; i < 4; i++) {
            v[i] = p[lane + 32 * i];
            ss += v[i].x * v[i].x + v[i].y * v[i].y + v[i].z * v[i].z + v[i].w * v[i].w;
        }
#pragma unroll
        for (int o = 16; o > 0; o >>= 1) ss += __shfl_xor_sync(0xffffffffu, ss, o);
        float inv = 1.0f / fmaxf(sqrtf(ss), 1e-12f);
        uint2* qp = a.xout_p[t] + (size_t)row * 128;
        uint2* qn = a.xout_n[t] + (size_t)row * 128;
#pragma unroll
        for (int i = 0; i < 4; i++) {
            qp[lane + 32 * i] = make_uint2(pack_h2(v[i].x, v[i].y),
                                           pack_h2(v[i].z, v[i].w));
            qn[lane + 32 * i] = make_uint2(pack_h2(v[i].x * inv, v[i].y * inv),
                                           pack_h2(v[i].z * inv, v[i].w * inv));
        }
        return;
    }
    size_t i = (size_t)(blockIdx.x - a.nW - a.nX) * blockDim.x + threadIdx.x;
    size_t stride = (size_t)(gridDim.x - a.nW - a.nX) * blockDim.x;
    for (; i < a.zn4; i += stride)
        a.zbase[i] = make_float4(0.f, 0.f, 0.f, 0.f);
}

// ---------------------------------------------------------------------------
// k2: scatter — gather half x, fp32 red. 64 lanes/edge, 4 edges/block.
// ---------------------------------------------------------------------------
struct ScatArgs {
    const int* ei[3];
    const __half* x[3];
    float* sum[3];
    float* cnt[3];
    int E[3];
    int b0, b01;
};

__global__ void scatter_all(ScatArgs a) {
    int b = blockIdx.x, t;
    if (b < a.b0)       { t = 0; }
    else if (b < a.b01) { t = 1; b -= a.b0; }
    else                { t = 2; b -= a.b01; }
    int e = b * 4 + (threadIdx.x >> 6);
    if (e >= a.E[t]) return;
    int lane = threadIdx.x & 63;
    int src = a.ei[t][e];
    int dst = a.ei[t][(size_t)a.E[t] + e];
    uint4 hv = *(const uint4*)(a.x[t] + (size_t)src * FD + lane * 8);
    float2 f0 = __half22float2(*(__half2*)&hv.x);
    float2 f1 = __half22float2(*(__half2*)&hv.y);
    float2 f2 = __half22float2(*(__half2*)&hv.z);
    float2 f3 = __half22float2(*(__half2*)&hv.w);
    float* o = a.sum[t] + (size_t)dst * FD + lane * 8;
    asm volatile("red.global.add.v4.f32 [%0], {%1,%2,%3,%4};"
                 :: "l"(o), "f"(f0.x), "f"(f0.y), "f"(f1.x), "f"(f1.y) : "memory");
    asm volatile("red.global.add.v4.f32 [%0], {%1,%2,%3,%4};"
                 :: "l"(o + 4), "f"(f2.x), "f"(f2.y), "f"(f3.x), "f"(f3.y) : "memory");
    if (lane == 0) atomicAdd(a.cnt[t] + dst, 1.0f);
}

// ---------------------------------------------------------------------------
// k3: finalize means -> half
// ---------------------------------------------------------------------------
struct FinArgs {
    const float4* sum[3];
    const float* cnt[3];
    uint2* outh[3];
    size_t n[3];
};

__global__ void finalize_all(FinArgs a) {
    size_t i = (size_t)blockIdx.x * blockDim.x + threadIdx.x;
    int t = 0;
    if (i >= a.n[0]) { i -= a.n[0]; t = 1; }
    if (t == 1 && i >= a.n[1]) { i -= a.n[1]; t = 2; }
    if (t == 2 && i >= a.n[2]) return;
    int row = (int)(i >> 7);
    float iv = 1.0f / fmaxf(a.cnt[t][row], 1.0f);
    float4 v = a.sum[t][i];
    a.outh[t][i] = make_uint2(pack_h2(v.x * iv, v.y * iv),
                              pack_h2(v.z * iv, v.w * iv));
}

// ---------------------------------------------------------------------------
// shared GEMM helpers
// ---------------------------------------------------------------------------
struct SegH {
    const __half* A[3];
    const __half* B[3];
    int ldb[3];
};

#define SROW_H 40

__device__ __forceinline__ void cp16s(uint32_t dst_smem, const void* src) {
    asm volatile("cp.async.cg.shared.global [%0], [%1], 16;"
                 :: "r"(dst_smem), "l"(src));
}
__device__ __forceinline__ uint32_t smem_u32(const void* p) {
    uint32_t a;
    asm("{ .reg .u64 t; cvta.to.shared.u64 t, %1; cvt.u32.u64 %0, t; }"
        : "=r"(a) : "l"(p));
    return a;
}
#define LDMX4(r0, r1, r2, r3, addr) \
    asm volatile("ldmatrix.sync.aligned.m8n8.x4.shared.b16 {%0,%1,%2,%3}, [%4];" \
                 : "=r"(r0), "=r"(r1), "=r"(r2), "=r"(r3) : "r"(addr))
#define MMA16816(acc, av, bv) \
    asm volatile( \
        "mma.sync.aligned.m16n8k16.row.col.f32.f16.f16.f32 " \
        "{%0,%1,%2,%3}, {%4,%5,%6,%7}, {%8,%9}, {%0,%1,%2,%3};" \
        : "+f"((acc)[0]), "+f"((acc)[1]), "+f"((acc)[2]), "+f"((acc)[3]) \
        : "r"((av)[0]), "r"((av)[1]), "r"((av)[2]), "r"((av)[3]), \
          "r"((bv)[0]), "r"((bv)[1]))

extern __shared__ __align__(128) unsigned char hsm[];

// ---------------------------------------------------------------------------
// Encoder GEMM: BM=64 x BN=512(full) x BK=32, 512 thr / 16 warps (2Mx8N),
// warp tile 32x64. A (half) + B via 4-stage cp.async.
// Epilogue: +bias, full-row L2 norm, write half normalized.
// ---------------------------------------------------------------------------
struct ProbE {
    SegH segs;
    int nseg;
    const float* bias;
    __half* Ch;
    int M;
};

#define E_NTHR 512
#define E_ASTG (64 * SROW_H * 2)          // 5120
#define E_BSTG (512 * SROW_H * 2)         // 40960
#define E_STG  (E_ASTG + E_BSTG)          // 46080
#define E_SMEM (4 * E_STG)                // 184320

__global__ __launch_bounds__(E_NTHR, 1) void gemm_enc(ProbE p0, ProbE p1, int split) {
    const bool first = (blockIdx.x < (unsigned)split);
    ProbE p = first ? p0 : p1;
    const int bm = (first ? blockIdx.x : blockIdx.x - split) * 64;

    const int tid  = threadIdx.x;
    const int lane = tid & 31;
    const int warp = tid >> 5;           // 0..15
    const int wm   = warp >> 3;          // 0..1 (M dir, 32 rows)
    const int wn   = warp & 7;           // 0..7 (N dir, 64 cols)
    const int g    = lane >> 2;
    const int t4   = lane & 3;

    const uint32_t dyn = smem_u32(hsm);
    __shared__ float rowss[64];

    const uint32_t aoff =
        (uint32_t)(((wm * 32 + (lane & 15)) * SROW_H + ((lane >> 4) << 3)) * 2);
    const uint32_t boff = E_ASTG +
        (uint32_t)(((wn * 64 + (lane & 7) + (((lane >> 4) & 1) << 3)) * SROW_H +
                    (((lane >> 3) & 1) << 3)) * 2);

    float acc[2][8][4];
#pragma unroll
    for (int mi = 0; mi < 2; mi++)
#pragma unroll
        for (int ni = 0; ni < 8; ni++)
#pragma unroll
            for (int r = 0; r < 4; r++) acc[mi][ni][r] = 0.f;

    const int NKB = p.nseg * (FD / 32);

    auto issue = [&](int kb) {
        const int st   = kb & 3;
        const int s    = kb >> 4;
        const int koff = (kb & 15) * 32;
        const uint32_t abase = dyn + st * E_STG;
        const uint32_t bbase = abase + E_ASTG;
        if (tid < 256) {   // A: 64 rows x 4 c16 = 256 jobs
            int row = tid >> 2, c16 = tid & 3;
            int r = bm + row;
            if (r < p.M)
                cp16s(abase + (uint32_t)(row * (SROW_H * 2) + c16 * 16),
                      p.segs.A[s] + (size_t)r * FD + koff + c16 * 8);
            else {
                uint32_t d = abase + (uint32_t)(row * (SROW_H * 2) + c16 * 16);
                asm volatile("st.shared.v4.u32 [%0], {%1,%1,%1,%1};"
                             :: "r"(d), "r"(0u));
            }
        }
        const __half* Bb = p.segs.B[s];
        const int ldb = p.segs.ldb[s];
#pragma unroll
        for (int i = 0; i < 4; i++) {    // B: 512 rows x 4 = 2048 jobs
            int u = tid + i * E_NTHR;
            int row = u >> 2, c16 = u & 3;
            cp16s(bbase + (uint32_t)(row * (SROW_H * 2) + c16 * 16),
                  Bb + (size_t)row * ldb + koff + c16 * 8);
        }
        asm volatile("cp.async.commit_group;");
    };

    issue(0);
    if (NKB > 1) issue(1);
    if (NKB > 2) issue(2);

    for (int c = 0; c < NKB; c++) {
        const int st = c & 3;
        if (c + 3 < NKB) issue(c + 3);
        const int rem = NKB - 1 - c;
        if (rem >= 3)      asm volatile("cp.async.wait_group 3;");
        else if (rem == 2) asm volatile("cp.async.wait_group 2;");
        else if (rem == 1) asm volatile("cp.async.wait_group 1;");
        else               asm volatile("cp.async.wait_group 0;");
        __syncthreads();

        const uint32_t stBase = dyn + st * E_STG;
#pragma unroll
        for (int ks = 0; ks < 2; ks++) {
            unsigned a[2][4], b[8][2];
#pragma unroll
            for (int mi = 0; mi < 2; mi++)
                LDMX4(a[mi][0], a[mi][1], a[mi][2], a[mi][3],
                      stBase + aoff + (uint32_t)(mi * 16 * SROW_H * 2 + ks * 32));
#pragma unroll
            for (int pi = 0; pi < 4; pi++)
                LDMX4(b[2 * pi][0], b[2 * pi][1], b[2 * pi + 1][0], b[2 * pi + 1][1],
                      stBase + boff + (uint32_t)(pi * 16 * SROW_H * 2 + ks * 32));
#pragma unroll
            for (int mi = 0; mi < 2; mi++)
#pragma unroll
                for (int ni = 0; ni < 8; ni++)
                    MMA16816(acc[mi][ni], a[mi], b[ni]);
        }
        __syncthreads();
    }

    // epilogue: +bias, row ssq over full 512 cols, normalize, write half
    float bb[8][2];
#pragma unroll
    for (int ni = 0; ni < 8; ni++) {
        int c = wn * 64 + ni * 8 + t4 * 2;
        bb[ni][0] = p.bias[c];
        bb[ni][1] = p.bias[c + 1];
    }
    if (tid < 64) rowss[tid] = 0.f;
    __syncthreads();
#pragma unroll
    for (int mi = 0; mi < 2; mi++) {
        float s0 = 0.f, s1 = 0.f;
#pragma unroll
        for (int ni = 0; ni < 8; ni++) {
            float v0 = acc[mi][ni][0] + bb[ni][0];
            float v1 = acc[mi][ni][1] + bb[ni][1];
            float v2 = acc[mi][ni][2] + bb[ni][0];
            float v3 = acc[mi][ni][3] + bb[ni][1];
            acc[mi][ni][0] = v0; acc[mi][ni][1] = v1;
            acc[mi][ni][2] = v2; acc[mi][ni][3] = v3;
            s0 += v0 * v0 + v1 * v1;
            s1 += v2 * v2 + v3 * v3;
        }
        s0 += __shfl_xor_sync(0xffffffffu, s0, 1);
        s0 += __shfl_xor_sync(0xffffffffu, s0, 2);
        s1 += __shfl_xor_sync(0xffffffffu, s1, 1);
        s1 += __shfl_xor_sync(0xffffffffu, s1, 2);
        if (t4 == 0) {
            atomicAdd(&rowss[wm * 32 + mi * 16 + g], s0);
            atomicAdd(&rowss[wm * 32 + mi * 16 + g + 8], s1);
        }
    }
    __syncthreads();
#pragma unroll
    for (int mi = 0; mi < 2; mi++) {
        const int r0 = wm * 32 + mi * 16 + g;
        const int gr0 = bm + r0;
        const float inv0 = 1.0f / fmaxf(sqrtf(rowss[r0]), 1e-12f);
        const float inv1 = 1.0f / fmaxf(sqrtf(rowss[r0 + 8]), 1e-12f);
#pragma unroll
        for (int ni = 0; ni < 8; ni++) {
            const int c = wn * 64 + ni * 8 + t4 * 2;
            if (gr0 < p.M)
                *(unsigned*)(p.Ch + (size_t)gr0 * FD + c) =
                    pack_h2(acc[mi][ni][0] * inv0, acc[mi][ni][1] * inv0);
            if (gr0 + 8 < p.M)
                *(unsigned*)(p.Ch + (size_t)(gr0 + 8) * FD + c) =
                    pack_h2(acc[mi][ni][2] * inv1, acc[mi][ni][3] * inv1);
        }
    }
}

// ---------------------------------------------------------------------------
// Decoder GEMM: 128x256x32, 512 thr / 16 warps, warp 64x32.
// ---------------------------------------------------------------------------
struct ProbH {
    SegH segs;
    int nseg;
    const float* bias;
    float* C;
    int M;
};

#define NTHR 512
#define A_BYTES_H (128 * SROW_H * 2)
#define B_BYTES_H (256 * SROW_H * 2)
#define STG_H (A_BYTES_H + B_BYTES_H)
#define GEMM_SMEM (4 * STG_H)

__global__ __launch_bounds__(NTHR, 1) void gemm_h(ProbH p0, ProbH p1, int split) {
    const bool first = (blockIdx.x < (unsigned)split);
    ProbH p = first ? p0 : p1;
    const int bm = (first ? blockIdx.x : blockIdx.x - split) * 128;
    const int bn = blockIdx.y * 256;

    const int tid  = threadIdx.x;
    const int lane = tid & 31;
    const int warp = tid >> 5;
    const int wm = warp >> 3;
    const int wn = warp & 7;
    const int g  = lane >> 2;
    const int t4 = lane & 3;

    const uint32_t dyn = smem_u32(hsm);

    const uint32_t aoff =
        (uint32_t)(((wm * 64 + (lane & 15)) * SROW_H + ((lane >> 4) << 3)) * 2);
    const uint32_t boff = A_BYTES_H +
        (uint32_t)(((wn * 32 + (lane & 7) + (((lane >> 4) & 1) << 3)) * SROW_H +
                    (((lane >> 3) & 1) << 3)) * 2);

    float acc[4][4][4];
#pragma unroll
    for (int mi = 0; mi < 4; mi++)
#pragma unroll
        for (int ni = 0; ni < 4; ni++)
#pragma unroll
            for (int r = 0; r < 4; r++) acc[mi][ni][r] = 0.f;

    const int NKB = p.nseg * (FD / 32);

    auto issue = [&](int kb) {
        const int st   = kb & 3;
        const int s    = kb >> 4;
        const int koff = (kb & 15) * 32;
        const uint32_t abase = dyn + st * STG_H;
        const uint32_t bbase = abase + A_BYTES_H;
        {
            int row = tid >> 2, c16 = tid & 3;
            int r = bm + row;
            if (r < p.M)
                cp16s(abase + (uint32_t)(row * (SROW_H * 2) + c16 * 16),
                      p.segs.A[s] + (size_t)r * FD + koff + c16 * 8);
            else {
                uint32_t d = abase + (uint32_t)(row * (SROW_H * 2) + c16 * 16);
                asm volatile("st.shared.v4.u32 [%0], {%1,%1,%1,%1};"
                             :: "r"(d), "r"(0u));
            }
        }
        const __half* Bb = p.segs.B[s];
        const int ldb = p.segs.ldb[s];
#pragma unroll
        for (int i = 0; i < 2; i++) {
            int u = tid + i * NTHR;
            int row = u >> 2, c16 = u & 3;
            cp16s(bbase + (uint32_t)(row * (SROW_H * 2) + c16 * 16),
                  Bb + (size_t)(bn + row) * ldb + koff + c16 * 8);
        }
        asm volatile("cp.async.commit_group;");
    };

    issue(0);
    if (NKB > 1) issue(1);
    if (NKB > 2) issue(2);

    for (int c = 0; c < NKB; c++) {
        const int st = c & 3;
        if (c + 3 < NKB) issue(c + 3);
        const int rem = NKB - 1 - c;
        if (rem >= 3)      asm volatile("cp.async.wait_group 3;");
        else if (rem == 2) asm volatile("cp.async.wait_group 2;");
        else if (rem == 1) asm volatile("cp.async.wait_group 1;");
        else               asm volatile("cp.async.wait_group 0;");
        __syncthreads();

        const uint32_t stBase = dyn + st * STG_H;
#pragma unroll
        for (int ks = 0; ks < 2; ks++) {
            unsigned a[4][4], b[4][2];
#pragma unroll
            for (int mi = 0; mi < 4; mi++)
                LDMX4(a[mi][0], a[mi][1], a[mi][2], a[mi][3],
                      stBase + aoff + (uint32_t)(mi * 16 * SROW_H * 2 + ks * 32));
#pragma unroll
            for (int pi = 0; pi < 2; pi++)
                LDMX4(b[2 * pi][0], b[2 * pi][1], b[2 * pi + 1][0], b[2 * pi + 1][1],
                      stBase + boff + (uint32_t)(pi * 16 * SROW_H * 2 + ks * 32));
#pragma unroll
            for (int mi = 0; mi < 4; mi++)
#pragma unroll
                for (int ni = 0; ni < 4; ni++)
                    MMA16816(acc[mi][ni], a[mi], b[ni]);
        }
        __syncthreads();
    }

#pragma unroll
    for (int ni = 0; ni < 4; ni++) {
        const int c = bn + wn * 32 + ni * 8 + t4 * 2;
        const float bb0 = p.bias[c];
        const float bb1 = p.bias[c + 1];
#pragma unroll
        for (int mi = 0; mi < 4; mi++) {
            const int r0 = bm + wm * 64 + mi * 16 + g;
            if (r0 < p.M)
                *(float2*)(p.C + (size_t)r0 * FD + c) =
                    make_float2(acc[mi][ni][0] + bb0, acc[mi][ni][1] + bb1);
            const int r1 = r0 + 8;
            if (r1 < p.M)
                *(float2*)(p.C + (size_t)r1 * FD + c) =
                    make_float2(acc[mi][ni][2] + bb0, acc[mi][ni][3] + bb1);
        }
    }
}

// ---------------------------------------------------------------------------
// kernel_launch — 5 launches
// ---------------------------------------------------------------------------
extern "C" void kernel_launch(void* const* d_in, const int* in_sizes, int n_in,
                              void* d_out, int out_size) {
    const float* x_paper   = (const float*)d_in[0];
    const float* x_dataset = (const float*)d_in[1];
    const int*   ei_pp     = (const int*)d_in[2];
    const int*   ei_pd     = (const int*)d_in[3];
    const int*   ei_dp     = (const int*)d_in[4];
    const float* Wl_pp = (const float*)d_in[5];
    const float* Wr_pp = (const float*)d_in[6];
    const float* b_pp  = (const float*)d_in[7];
    const float* Wl_pd = (const float*)d_in[8];
    const float* Wr_pd = (const float*)d_in[9];
    const float* b_pd  = (const float*)d_in[10];
    const float* Wl_dp = (const float*)d_in[11];
    const float* Wr_dp = (const float*)d_in[12];
    const float* b_dp  = (const float*)d_in[13];
    const float* Wdec_p = (const float*)d_in[14];
    const float* bdec_p = (const float*)d_in[15];
    const float* Wdec_d = (const float*)d_in[16];
    const float* bdec_d = (const float*)d_in[17];

    const int Epp = in_sizes[2] / 2;
    const int Epd = in_sizes[3] / 2;
    const int Edp = in_sizes[4] / 2;

    float* out = (float*)d_out;

    unsigned* base = nullptr;
    cudaGetSymbolAddress((void**)&base, g_scratch);
    float*    sum_pp = (float*)(base + U_SUM_PP);
    float*    sum_dp = (float*)(base + U_SUM_DP);
    float*    sum_pd = (float*)(base + U_SUM_PD);
    float*    cnt_pp = (float*)(base + U_CNT_PP);
    float*    cnt_dp = (float*)(base + U_CNT_DP);
    float*    cnt_pd = (float*)(base + U_CNT_PD);
    __half*   mh_pp  = (__half*)(base + U_MH_PP);
    __half*   mh_dp  = (__half*)(base + U_MH_DP);
    __half*   mh_pd  = (__half*)(base + U_MH_PD);
    __half*   xh_p   = (__half*)(base + U_XH_P);
    __half*   xh_d   = (__half*)(base + U_XH_D);
    __half*   xnh_p  = (__half*)(base + U_XNH_P);
    __half*   xnh_d  = (__half*)(base + U_XNH_D);
    __half*   rech_p = (__half*)(base + U_RECH_P);
    __half*   rech_d = (__half*)(base + U_RECH_D);
    __half*   wcomb  = (__half*)(base + U_WCOMB);
    __half*   wrpp   = (__half*)(base + U_WRPP);
    __half*   wrdp   = (__half*)(base + U_WRDP);
    __half*   wrpd   = (__half*)(base + U_WRPD);
    __half*   wlpd   = (__half*)(base + U_WLPD);
    __half*   wdecp  = (__half*)(base + U_WDECP);
    __half*   wdecd  = (__half*)(base + U_WDECD);
    float*    bsum   = (float*)(base + U_BSUM);

    cudaFuncSetAttribute(gemm_enc, cudaFuncAttributeMaxDynamicSharedMemorySize,
                         E_SMEM);
    cudaFuncSetAttribute(gemm_h, cudaFuncAttributeMaxDynamicSharedMemorySize,
                         GEMM_SMEM);

    // k1: zero + weight prep + x -> half (plain + normalized)
    PrepArgs pa;
    pa.wlpp = Wl_pp; pa.wldp = Wl_dp; pa.wrpp = Wr_pp; pa.wrdp = Wr_dp;
    pa.wrpd = Wr_pd; pa.wlpd = Wl_pd; pa.wdecp = Wdec_p; pa.wdecd = Wdec_d;
    pa.bpp = b_pp; pa.bdp = b_dp;
    pa.o_wcomb = (unsigned*)wcomb; pa.o_wrpp = (unsigned*)wrpp;
    pa.o_wrdp = (unsigned*)wrdp; pa.o_wrpd = (unsigned*)wrpd;
    pa.o_wlpd = (unsigned*)wlpd; pa.o_wdecp = (unsigned*)wdecp;
    pa.o_wdecd = (unsigned*)wdecd; pa.o_bsum = bsum;
    pa.xin[0] = x_paper;   pa.xout_p[0] = (uint2*)xh_p; pa.xout_n[0] = (uint2*)xnh_p; pa.xrows[0] = NP;
    pa.xin[1] = x_dataset; pa.xout_p[1] = (uint2*)xh_d; pa.xout_n[1] = (uint2*)xnh_d; pa.xrows[1] = ND;
    pa.zbase = (float4*)base; pa.zn4 = ZERO_END / 4;
    pa.nW = (unsigned)((FD * FD + 255) / 256);
    pa.nX = (unsigned)(((size_t)(NP + ND) * 32 + 255) / 256);
    zero_prep<<<pa.nW + pa.nX + 4096, 256>>>(pa);

    // k2: scatter (gathers half x)
    ScatArgs sa;
    sa.ei[0] = ei_pp; sa.x[0] = xh_p; sa.sum[0] = sum_pp; sa.cnt[0] = cnt_pp; sa.E[0] = Epp;
    sa.ei[1] = ei_dp; sa.x[1] = xh_d; sa.sum[1] = sum_dp; sa.cnt[1] = cnt_dp; sa.E[1] = Edp;
    sa.ei[2] = ei_pd; sa.x[2] = xh_p; sa.sum[2] = sum_pd; sa.cnt[2] = cnt_pd; sa.E[2] = Epd;
    int nb0 = (Epp + 3) / 4, nb1 = (Edp + 3) / 4, nb2 = (Epd + 3) / 4;
    sa.b0 = nb0; sa.b01 = nb0 + nb1;
    scatter_all<<<nb0 + nb1 + nb2, 256>>>(sa);

    // k3: finalize means -> half
    FinArgs fa;
    fa.sum[0] = (const float4*)sum_pp; fa.cnt[0] = cnt_pp; fa.outh[0] = (uint2*)mh_pp; fa.n[0] = (size_t)NP * 128;
    fa.sum[1] = (const float4*)sum_dp; fa.cnt[1] = cnt_dp; fa.outh[1] = (uint2*)mh_dp; fa.n[1] = (size_t)NP * 128;
    fa.sum[2] = (const float4*)sum_pd; fa.cnt[2] = cnt_pd; fa.outh[2] = (uint2*)mh_pd; fa.n[2] = (size_t)ND * 128;
    size_t ftot = fa.n[0] + fa.n[1] + fa.n[2];
    finalize_all<<<(int)((ftot + 255) / 256), 256>>>(fa);

    // k4: encoder GEMMs, fused L2-norm epilogue -> rech (half)
    const int gpe = (NP + 63) / 64;   // 782
    const int gde = (ND + 63) / 64;   // 79
    ProbE e0 = {}, e1 = {};
    e0.segs.A[0] = mh_pp; e0.segs.B[0] = wrpp;  e0.segs.ldb[0] = FD;
    e0.segs.A[1] = mh_dp; e0.segs.B[1] = wrdp;  e0.segs.ldb[1] = FD;
    e0.segs.A[2] = xh_p;  e0.segs.B[2] = wcomb; e0.segs.ldb[2] = FD;
    e0.nseg = 3; e0.bias = bsum; e0.Ch = rech_p; e0.M = NP;
    e1.segs.A[0] = mh_pd; e1.segs.B[0] = wrpd; e1.segs.ldb[0] = FD;
    e1.segs.A[1] = xh_d;  e1.segs.B[1] = wlpd; e1.segs.ldb[1] = FD;
    e1.nseg = 2; e1.bias = b_pd; e1.Ch = rech_d; e1.M = ND;
    gemm_enc<<<gpe + gde, E_NTHR, E_SMEM>>>(e0, e1, gpe);

    // k5: decoder GEMMs -> out (fp32)
    const int gp = (NP + 127) / 128;
    const int gd = (ND + 127) / 128;
    dim3 ggrid(gp + gd, FD / 256);
    ProbH d0 = {}, d1 = {};
    d0.segs.A[0] = rech_p; d0.segs.B[0] = wdecp;      d0.segs.ldb[0] = 2 * FD;
    d0.segs.A[1] = xnh_p;  d0.segs.B[1] = wdecp + FD; d0.segs.ldb[1] = 2 * FD;
    d0.nseg = 2; d0.bias = bdec_p; d0.C = out; d0.M = NP;
    d1.segs.A[0] = rech_d; d1.segs.B[0] = wdecd;      d1.segs.ldb[0] = 2 * FD;
    d1.segs.A[1] = xnh_d;  d1.segs.B[1] = wdecd + FD; d1.segs.ldb[1] = 2 * FD;
    d1.nseg = 2; d1.bias = bdec_d; d1.C = out + (size_t)NP * FD; d1.M = ND;
    gemm_h<<<ggrid, NTHR, GEMM_SMEM>>>(d0, d1, gp);
}

// round 14
// speedup vs baseline: 1.0813x; 1.0545x over previous
#include <cuda_runtime.h>
#include <cuda_fp16.h>
#include <math.h>
#include <stdint.h>

#define NP 50000
#define ND 5000
#define FD 512

// ---------------------------------------------------------------------------
// Scratch (u32 units)
// ---------------------------------------------------------------------------
constexpr size_t NPF   = (size_t)NP * FD;
constexpr size_t NDF   = (size_t)ND * FD;
constexpr size_t U_SUM_PP = 0;
constexpr size_t U_SUM_DP = U_SUM_PP + NPF;
constexpr size_t U_SUM_PD = U_SUM_DP + NPF;
constexpr size_t U_CNT_PP = U_SUM_PD + NDF;
constexpr size_t U_CNT_DP = U_CNT_PP + NP;
constexpr size_t U_CNT_PD = U_CNT_DP + NP;
constexpr size_t ZERO_END = U_CNT_PD + ND;
constexpr size_t U_MH_PP  = (ZERO_END + 1) & ~(size_t)1;
constexpr size_t U_MH_DP  = U_MH_PP + NPF / 2;
constexpr size_t U_MH_PD  = U_MH_DP + NPF / 2;
constexpr size_t U_XH_P   = U_MH_PD + NDF / 2;     // half x (plain)
constexpr size_t U_XH_D   = U_XH_P + NPF / 2;
constexpr size_t U_XNH_P  = U_XH_D + NDF / 2;      // half x (normalized)
constexpr size_t U_XNH_D  = U_XNH_P + NPF / 2;
constexpr size_t U_RECH_P = U_XNH_D + NDF / 2;     // half rec (normalized)
constexpr size_t U_RECH_D = U_RECH_P + NPF / 2;
constexpr size_t U_WCOMB  = U_RECH_D + NDF / 2;
constexpr size_t U_WRPP   = U_WCOMB + (size_t)FD * FD / 2;
constexpr size_t U_WRDP   = U_WRPP + (size_t)FD * FD / 2;
constexpr size_t U_WRPD   = U_WRDP + (size_t)FD * FD / 2;
constexpr size_t U_WLPD   = U_WRPD + (size_t)FD * FD / 2;
constexpr size_t U_WDECP  = U_WLPD + (size_t)FD * FD / 2;
constexpr size_t U_WDECD  = U_WDECP + (size_t)FD * FD;
constexpr size_t U_BSUM   = U_WDECD + (size_t)FD * FD;
constexpr size_t U_TOTAL  = U_BSUM + FD;

__device__ __align__(16) unsigned g_scratch[U_TOTAL];

__device__ __forceinline__ unsigned pack_h2(float a, float b) {
    __half2 h = __floats2half2_rn(a, b);
    return *reinterpret_cast<unsigned*>(&h);
}

// ---------------------------------------------------------------------------
// k1: zero + weight prep + x -> half (plain + normalized), phased grid
// ---------------------------------------------------------------------------
struct PrepArgs {
    const float *wlpp, *wldp, *wrpp, *wrdp, *wrpd, *wlpd, *wdecp, *wdecd, *bpp, *bdp;
    unsigned *o_wcomb, *o_wrpp, *o_wrdp, *o_wrpd, *o_wlpd, *o_wdecp, *o_wdecd;
    float* o_bsum;
    const float* xin[2];
    uint2* xout_p[2];
    uint2* xout_n[2];
    int xrows[2];
    float4* zbase;
    size_t zn4;
    unsigned nW, nX;
};

__global__ void zero_prep(PrepArgs a) {
    if (blockIdx.x < a.nW) {
        size_t idx = (size_t)blockIdx.x * blockDim.x + threadIdx.x;
        const int nh = FD * FD / 2;
        if (idx < (size_t)nh) {
            int j = 2 * (int)idx;
            a.o_wcomb[idx] = pack_h2(a.wlpp[j] + a.wldp[j], a.wlpp[j + 1] + a.wldp[j + 1]);
            a.o_wrpp[idx]  = pack_h2(a.wrpp[j], a.wrpp[j + 1]);
            a.o_wrdp[idx]  = pack_h2(a.wrdp[j], a.wrdp[j + 1]);
            a.o_wrpd[idx]  = pack_h2(a.wrpd[j], a.wrpd[j + 1]);
            a.o_wlpd[idx]  = pack_h2(a.wlpd[j], a.wlpd[j + 1]);
        }
        if (idx < (size_t)(2 * nh)) {
            int j = 2 * (int)idx;
            a.o_wdecp[idx] = pack_h2(a.wdecp[j], a.wdecp[j + 1]);
            a.o_wdecd[idx] = pack_h2(a.wdecd[j], a.wdecd[j + 1]);
        }
        if (idx < FD) a.o_bsum[idx] = a.bpp[idx] + a.bdp[idx];
        return;
    }
    if (blockIdx.x < a.nW + a.nX) {
        int row = (int)((((size_t)(blockIdx.x - a.nW) * blockDim.x) + threadIdx.x) >> 5);
        int t = 0;
        if (row >= a.xrows[0]) { row -= a.xrows[0]; t = 1; }
        if (t == 1 && row >= a.xrows[1]) return;
        int lane = threadIdx.x & 31;
        const float4* p = (const float4*)(a.xin[t] + (size_t)row * FD);
        float4 v[4];
        float ss = 0.f;
#pragma unroll
        for (int i = 0; i < 4; i++) {
            v[i] = p[lane + 32 * i];
            ss += v[i].x * v[i].x + v[i].y * v[i].y + v[i].z * v[i].z + v[i].w * v[i].w;
        }
#pragma unroll
        for (int o = 16; o > 0; o >>= 1) ss += __shfl_xor_sync(0xffffffffu, ss, o);
        float inv = 1.0f / fmaxf(sqrtf(ss), 1e-12f);
        uint2* qp = a.xout_p[t] + (size_t)row * 128;
        uint2* qn = a.xout_n[t] + (size_t)row * 128;
#pragma unroll
        for (int i = 0; i < 4; i++) {
            qp[lane + 32 * i] = make_uint2(pack_h2(v[i].x, v[i].y),
                                           pack_h2(v[i].z, v[i].w));
            qn[lane + 32 * i] = make_uint2(pack_h2(v[i].x * inv, v[i].y * inv),
                                           pack_h2(v[i].z * inv, v[i].w * inv));
        }
        return;
    }
    size_t i = (size_t)(blockIdx.x - a.nW - a.nX) * blockDim.x + threadIdx.x;
    size_t stride = (size_t)(gridDim.x - a.nW - a.nX) * blockDim.x;
    for (; i < a.zn4; i += stride)
        a.zbase[i] = make_float4(0.f, 0.f, 0.f, 0.f);
}

// ---------------------------------------------------------------------------
// k2: scatter — gather half x, fp32 red. 64 lanes/edge, 4 edges/block.
// ---------------------------------------------------------------------------
struct ScatArgs {
    const int* ei[3];
    const __half* x[3];
    float* sum[3];
    float* cnt[3];
    int E[3];
    int b0, b01;
};

__global__ void scatter_all(ScatArgs a) {
    int b = blockIdx.x, t;
    if (b < a.b0)       { t = 0; }
    else if (b < a.b01) { t = 1; b -= a.b0; }
    else                { t = 2; b -= a.b01; }
    int e = b * 4 + (threadIdx.x >> 6);
    if (e >= a.E[t]) return;
    int lane = threadIdx.x & 63;
    int src = a.ei[t][e];
    int dst = a.ei[t][(size_t)a.E[t] + e];
    uint4 hv = *(const uint4*)(a.x[t] + (size_t)src * FD + lane * 8);
    float2 f0 = __half22float2(*(__half2*)&hv.x);
    float2 f1 = __half22float2(*(__half2*)&hv.y);
    float2 f2 = __half22float2(*(__half2*)&hv.z);
    float2 f3 = __half22float2(*(__half2*)&hv.w);
    float* o = a.sum[t] + (size_t)dst * FD + lane * 8;
    asm volatile("red.global.add.v4.f32 [%0], {%1,%2,%3,%4};"
                 :: "l"(o), "f"(f0.x), "f"(f0.y), "f"(f1.x), "f"(f1.y) : "memory");
    asm volatile("red.global.add.v4.f32 [%0], {%1,%2,%3,%4};"
                 :: "l"(o + 4), "f"(f2.x), "f"(f2.y), "f"(f3.x), "f"(f3.y) : "memory");
    if (lane == 0) atomicAdd(a.cnt[t] + dst, 1.0f);
}

// ---------------------------------------------------------------------------
// k3: finalize means -> half, vectorized: 1 uint4 out (8 elems) per thread
// ---------------------------------------------------------------------------
struct FinArgs {
    const float4* sum[3];
    const float* cnt[3];
    uint4* outh[3];
    size_t n[3];       // uint4 jobs per region (= rows * 64)
};

__global__ void finalize_all(FinArgs a) {
    size_t i = (size_t)blockIdx.x * blockDim.x + threadIdx.x;
    int t = 0;
    if (i >= a.n[0]) { i -= a.n[0]; t = 1; }
    if (t == 1 && i >= a.n[1]) { i -= a.n[1]; t = 2; }
    if (t == 2 && i >= a.n[2]) return;
    int row = (int)(i >> 6);                  // 64 uint4 per row
    float iv = 1.0f / fmaxf(a.cnt[t][row], 1.0f);
    const float4* s = a.sum[t] + 2 * i;
    float4 v0 = s[0];
    float4 v1 = s[1];
    a.outh[t][i] = make_uint4(pack_h2(v0.x * iv, v0.y * iv),
                              pack_h2(v0.z * iv, v0.w * iv),
                              pack_h2(v1.x * iv, v1.y * iv),
                              pack_h2(v1.z * iv, v1.w * iv));
}

// ---------------------------------------------------------------------------
// shared GEMM helpers
// ---------------------------------------------------------------------------
struct SegH {
    const __half* A[3];
    const __half* B[3];
    int ldb[3];
};

#define SROW_H 40

__device__ __forceinline__ void cp16s(uint32_t dst_smem, const void* src) {
    asm volatile("cp.async.cg.shared.global [%0], [%1], 16;"
                 :: "r"(dst_smem), "l"(src));
}
__device__ __forceinline__ uint32_t smem_u32(const void* p) {
    uint32_t a;
    asm("{ .reg .u64 t; cvta.to.shared.u64 t, %1; cvt.u32.u64 %0, t; }"
        : "=r"(a) : "l"(p));
    return a;
}
#define LDMX4(r0, r1, r2, r3, addr) \
    asm volatile("ldmatrix.sync.aligned.m8n8.x4.shared.b16 {%0,%1,%2,%3}, [%4];" \
                 : "=r"(r0), "=r"(r1), "=r"(r2), "=r"(r3) : "r"(addr))
#define MMA16816(acc, av, bv) \
    asm volatile( \
        "mma.sync.aligned.m16n8k16.row.col.f32.f16.f16.f32 " \
        "{%0,%1,%2,%3}, {%4,%5,%6,%7}, {%8,%9}, {%0,%1,%2,%3};" \
        : "+f"((acc)[0]), "+f"((acc)[1]), "+f"((acc)[2]), "+f"((acc)[3]) \
        : "r"((av)[0]), "r"((av)[1]), "r"((av)[2]), "r"((av)[3]), \
          "r"((bv)[0]), "r"((bv)[1]))

extern __shared__ __align__(128) unsigned char hsm[];

// ---------------------------------------------------------------------------
// Encoder GEMM (R11 config): BM=64 x BN=512(full) x BK=32, 256 thr / 8 warps
// (1x8), warp tile 64x64. A (half) + B via 4-stage cp.async.
// Epilogue: +bias, full-row L2 norm, write half normalized.
// ---------------------------------------------------------------------------
struct ProbE {
    SegH segs;
    int nseg;
    const float* bias;
    __half* Ch;
    int M;
};

#define E_ASTG (64 * SROW_H * 2)          // 5120
#define E_BSTG (512 * SROW_H * 2)         // 40960
#define E_STG  (E_ASTG + E_BSTG)          // 46080
#define E_SMEM (4 * E_STG)                // 184320

__global__ __launch_bounds__(256, 1) void gemm_enc(ProbE p0, ProbE p1, int split) {
    const bool first = (blockIdx.x < (unsigned)split);
    ProbE p = first ? p0 : p1;
    const int bm = (first ? blockIdx.x : blockIdx.x - split) * 64;

    const int tid  = threadIdx.x;
    const int lane = tid & 31;
    const int wn   = tid >> 5;           // 0..7
    const int g    = lane >> 2;
    const int t4   = lane & 3;

    const uint32_t dyn = smem_u32(hsm);
    __shared__ float rowss[64];

    const uint32_t aoff =
        (uint32_t)(((lane & 15) * SROW_H + ((lane >> 4) << 3)) * 2);
    const uint32_t boff = E_ASTG +
        (uint32_t)(((wn * 64 + (lane & 7) + (((lane >> 4) & 1) << 3)) * SROW_H +
                    (((lane >> 3) & 1) << 3)) * 2);

    float acc[4][8][4];
#pragma unroll
    for (int mi = 0; mi < 4; mi++)
#pragma unroll
        for (int ni = 0; ni < 8; ni++)
#pragma unroll
            for (int r = 0; r < 4; r++) acc[mi][ni][r] = 0.f;

    const int NKB = p.nseg * (FD / 32);

    auto issue = [&](int kb) {
        const int st   = kb & 3;
        const int s    = kb >> 4;
        const int koff = (kb & 15) * 32;
        const uint32_t abase = dyn + st * E_STG;
        const uint32_t bbase = abase + E_ASTG;
        {   // A: 64 rows x 4 c16 = 256 jobs (1/thread)
            int row = tid >> 2, c16 = tid & 3;
            int r = bm + row;
            if (r < p.M)
                cp16s(abase + (uint32_t)(row * (SROW_H * 2) + c16 * 16),
                      p.segs.A[s] + (size_t)r * FD + koff + c16 * 8);
            else {
                uint32_t d = abase + (uint32_t)(row * (SROW_H * 2) + c16 * 16);
                asm volatile("st.shared.v4.u32 [%0], {%1,%1,%1,%1};"
                             :: "r"(d), "r"(0u));
            }
        }
        const __half* Bb = p.segs.B[s];
        const int ldb = p.segs.ldb[s];
#pragma unroll
        for (int i = 0; i < 8; i++) {    // B: 512 rows x 4 = 2048 jobs (8/thread)
            int u = tid + i * 256;
            int row = u >> 2, c16 = u & 3;
            cp16s(bbase + (uint32_t)(row * (SROW_H * 2) + c16 * 16),
                  Bb + (size_t)row * ldb + koff + c16 * 8);
        }
        asm volatile("cp.async.commit_group;");
    };

    issue(0);
    if (NKB > 1) issue(1);
    if (NKB > 2) issue(2);

    for (int c = 0; c < NKB; c++) {
        const int st = c & 3;
        if (c + 3 < NKB) issue(c + 3);
        const int rem = NKB - 1 - c;
        if (rem >= 3)      asm volatile("cp.async.wait_group 3;");
        else if (rem == 2) asm volatile("cp.async.wait_group 2;");
        else if (rem == 1) asm volatile("cp.async.wait_group 1;");
        else               asm volatile("cp.async.wait_group 0;");
        __syncthreads();

        const uint32_t stBase = dyn + st * E_STG;
#pragma unroll
        for (int ks = 0; ks < 2; ks++) {
            unsigned a[4][4], b[8][2];
#pragma unroll
            for (int mi = 0; mi < 4; mi++)
                LDMX4(a[mi][0], a[mi][1], a[mi][2], a[mi][3],
                      stBase + aoff + (uint32_t)(mi * 16 * SROW_H * 2 + ks * 32));
#pragma unroll
            for (int pi = 0; pi < 4; pi++)
                LDMX4(b[2 * pi][0], b[2 * pi][1], b[2 * pi + 1][0], b[2 * pi + 1][1],
                      stBase + boff + (uint32_t)(pi * 16 * SROW_H * 2 + ks * 32));
#pragma unroll
            for (int mi = 0; mi < 4; mi++)
#pragma unroll
                for (int ni = 0; ni < 8; ni++)
                    MMA16816(acc[mi][ni], a[mi], b[ni]);
        }
        __syncthreads();
    }

    // epilogue: +bias, row ssq over full 512 cols, normalize, write half
    float bb[8][2];
#pragma unroll
    for (int ni = 0; ni < 8; ni++) {
        int c = wn * 64 + ni * 8 + t4 * 2;
        bb[ni][0] = p.bias[c];
        bb[ni][1] = p.bias[c + 1];
    }
    if (tid < 64) rowss[tid] = 0.f;
    __syncthreads();
#pragma unroll
    for (int mi = 0; mi < 4; mi++) {
        float s0 = 0.f, s1 = 0.f;
#pragma unroll
        for (int ni = 0; ni < 8; ni++) {
            float v0 = acc[mi][ni][0] + bb[ni][0];
            float v1 = acc[mi][ni][1] + bb[ni][1];
            float v2 = acc[mi][ni][2] + bb[ni][0];
            float v3 = acc[mi][ni][3] + bb[ni][1];
            acc[mi][ni][0] = v0; acc[mi][ni][1] = v1;
            acc[mi][ni][2] = v2; acc[mi][ni][3] = v3;
            s0 += v0 * v0 + v1 * v1;
            s1 += v2 * v2 + v3 * v3;
        }
        s0 += __shfl_xor_sync(0xffffffffu, s0, 1);
        s0 += __shfl_xor_sync(0xffffffffu, s0, 2);
        s1 += __shfl_xor_sync(0xffffffffu, s1, 1);
        s1 += __shfl_xor_sync(0xffffffffu, s1, 2);
        if (t4 == 0) {
            atomicAdd(&rowss[mi * 16 + g], s0);
            atomicAdd(&rowss[mi * 16 + g + 8], s1);
        }
    }
    __syncthreads();
#pragma unroll
    for (int mi = 0; mi < 4; mi++) {
        const int r0 = mi * 16 + g;
        const int gr0 = bm + r0;
        const float inv0 = 1.0f / fmaxf(sqrtf(rowss[r0]), 1e-12f);
        const float inv1 = 1.0f / fmaxf(sqrtf(rowss[r0 + 8]), 1e-12f);
#pragma unroll
        for (int ni = 0; ni < 8; ni++) {
            const int c = wn * 64 + ni * 8 + t4 * 2;
            if (gr0 < p.M)
                *(unsigned*)(p.Ch + (size_t)gr0 * FD + c) =
                    pack_h2(acc[mi][ni][0] * inv0, acc[mi][ni][1] * inv0);
            if (gr0 + 8 < p.M)
                *(unsigned*)(p.Ch + (size_t)(gr0 + 8) * FD + c) =
                    pack_h2(acc[mi][ni][2] * inv1, acc[mi][ni][3] * inv1);
        }
    }
}

// ---------------------------------------------------------------------------
// Decoder GEMM: 128x256x32, 512 thr / 16 warps, warp 64x32.
// ---------------------------------------------------------------------------
struct ProbH {
    SegH segs;
    int nseg;
    const float* bias;
    float* C;
    int M;
};

#define NTHR 512
#define A_BYTES_H (128 * SROW_H * 2)
#define B_BYTES_H (256 * SROW_H * 2)
#define STG_H (A_BYTES_H + B_BYTES_H)
#define GEMM_SMEM (4 * STG_H)

__global__ __launch_bounds__(NTHR, 1) void gemm_h(ProbH p0, ProbH p1, int split) {
    const bool first = (blockIdx.x < (unsigned)split);
    ProbH p = first ? p0 : p1;
    const int bm = (first ? blockIdx.x : blockIdx.x - split) * 128;
    const int bn = blockIdx.y * 256;

    const int tid  = threadIdx.x;
    const int lane = tid & 31;
    const int warp = tid >> 5;
    const int wm = warp >> 3;
    const int wn = warp & 7;
    const int g  = lane >> 2;
    const int t4 = lane & 3;

    const uint32_t dyn = smem_u32(hsm);

    const uint32_t aoff =
        (uint32_t)(((wm * 64 + (lane & 15)) * SROW_H + ((lane >> 4) << 3)) * 2);
    const uint32_t boff = A_BYTES_H +
        (uint32_t)(((wn * 32 + (lane & 7) + (((lane >> 4) & 1) << 3)) * SROW_H +
                    (((lane >> 3) & 1) << 3)) * 2);

    float acc[4][4][4];
#pragma unroll
    for (int mi = 0; mi < 4; mi++)
#pragma unroll
        for (int ni = 0; ni < 4; ni++)
#pragma unroll
            for (int r = 0; r < 4; r++) acc[mi][ni][r] = 0.f;

    const int NKB = p.nseg * (FD / 32);

    auto issue = [&](int kb) {
        const int st   = kb & 3;
        const int s    = kb >> 4;
        const int koff = (kb & 15) * 32;
        const uint32_t abase = dyn + st * STG_H;
        const uint32_t bbase = abase + A_BYTES_H;
        {
            int row = tid >> 2, c16 = tid & 3;
            int r = bm + row;
            if (r < p.M)
                cp16s(abase + (uint32_t)(row * (SROW_H * 2) + c16 * 16),
                      p.segs.A[s] + (size_t)r * FD + koff + c16 * 8);
            else {
                uint32_t d = abase + (uint32_t)(row * (SROW_H * 2) + c16 * 16);
                asm volatile("st.shared.v4.u32 [%0], {%1,%1,%1,%1};"
                             :: "r"(d), "r"(0u));
            }
        }
        const __half* Bb = p.segs.B[s];
        const int ldb = p.segs.ldb[s];
#pragma unroll
        for (int i = 0; i < 2; i++) {
            int u = tid + i * NTHR;
            int row = u >> 2, c16 = u & 3;
            cp16s(bbase + (uint32_t)(row * (SROW_H * 2) + c16 * 16),
                  Bb + (size_t)(bn + row) * ldb + koff + c16 * 8);
        }
        asm volatile("cp.async.commit_group;");
    };

    issue(0);
    if (NKB > 1) issue(1);
    if (NKB > 2) issue(2);

    for (int c = 0; c < NKB; c++) {
        const int st = c & 3;
        if (c + 3 < NKB) issue(c + 3);
        const int rem = NKB - 1 - c;
        if (rem >= 3)      asm volatile("cp.async.wait_group 3;");
        else if (rem == 2) asm volatile("cp.async.wait_group 2;");
        else if (rem == 1) asm volatile("cp.async.wait_group 1;");
        else               asm volatile("cp.async.wait_group 0;");
        __syncthreads();

        const uint32_t stBase = dyn + st * STG_H;
#pragma unroll
        for (int ks = 0; ks < 2; ks++) {
            unsigned a[4][4], b[4][2];
#pragma unroll
            for (int mi = 0; mi < 4; mi++)
                LDMX4(a[mi][0], a[mi][1], a[mi][2], a[mi][3],
                      stBase + aoff + (uint32_t)(mi * 16 * SROW_H * 2 + ks * 32));
#pragma unroll
            for (int pi = 0; pi < 2; pi++)
                LDMX4(b[2 * pi][0], b[2 * pi][1], b[2 * pi + 1][0], b[2 * pi + 1][1],
                      stBase + boff + (uint32_t)(pi * 16 * SROW_H * 2 + ks * 32));
#pragma unroll
            for (int mi = 0; mi < 4; mi++)
#pragma unroll
                for (int ni = 0; ni < 4; ni++)
                    MMA16816(acc[mi][ni], a[mi], b[ni]);
        }
        __syncthreads();
    }

#pragma unroll
    for (int ni = 0; ni < 4; ni++) {
        const int c = bn + wn * 32 + ni * 8 + t4 * 2;
        const float bb0 = p.bias[c];
        const float bb1 = p.bias[c + 1];
#pragma unroll
        for (int mi = 0; mi < 4; mi++) {
            const int r0 = bm + wm * 64 + mi * 16 + g;
            if (r0 < p.M)
                *(float2*)(p.C + (size_t)r0 * FD + c) =
                    make_float2(acc[mi][ni][0] + bb0, acc[mi][ni][1] + bb1);
            const int r1 = r0 + 8;
            if (r1 < p.M)
                *(float2*)(p.C + (size_t)r1 * FD + c) =
                    make_float2(acc[mi][ni][2] + bb0, acc[mi][ni][3] + bb1);
        }
    }
}

// ---------------------------------------------------------------------------
// kernel_launch — 5 launches
// ---------------------------------------------------------------------------
extern "C" void kernel_launch(void* const* d_in, const int* in_sizes, int n_in,
                              void* d_out, int out_size) {
    const float* x_paper   = (const float*)d_in[0];
    const float* x_dataset = (const float*)d_in[1];
    const int*   ei_pp     = (const int*)d_in[2];
    const int*   ei_pd     = (const int*)d_in[3];
    const int*   ei_dp     = (const int*)d_in[4];
    const float* Wl_pp = (const float*)d_in[5];
    const float* Wr_pp = (const float*)d_in[6];
    const float* b_pp  = (const float*)d_in[7];
    const float* Wl_pd = (const float*)d_in[8];
    const float* Wr_pd = (const float*)d_in[9];
    const float* b_pd  = (const float*)d_in[10];
    const float* Wl_dp = (const float*)d_in[11];
    const float* Wr_dp = (const float*)d_in[12];
    const float* b_dp  = (const float*)d_in[13];
    const float* Wdec_p = (const float*)d_in[14];
    const float* bdec_p = (const float*)d_in[15];
    const float* Wdec_d = (const float*)d_in[16];
    const float* bdec_d = (const float*)d_in[17];

    const int Epp = in_sizes[2] / 2;
    const int Epd = in_sizes[3] / 2;
    const int Edp = in_sizes[4] / 2;

    float* out = (float*)d_out;

    unsigned* base = nullptr;
    cudaGetSymbolAddress((void**)&base, g_scratch);
    float*    sum_pp = (float*)(base + U_SUM_PP);
    float*    sum_dp = (float*)(base + U_SUM_DP);
    float*    sum_pd = (float*)(base + U_SUM_PD);
    float*    cnt_pp = (float*)(base + U_CNT_PP);
    float*    cnt_dp = (float*)(base + U_CNT_DP);
    float*    cnt_pd = (float*)(base + U_CNT_PD);
    __half*   mh_pp  = (__half*)(base + U_MH_PP);
    __half*   mh_dp  = (__half*)(base + U_MH_DP);
    __half*   mh_pd  = (__half*)(base + U_MH_PD);
    __half*   xh_p   = (__half*)(base + U_XH_P);
    __half*   xh_d   = (__half*)(base + U_XH_D);
    __half*   xnh_p  = (__half*)(base + U_XNH_P);
    __half*   xnh_d  = (__half*)(base + U_XNH_D);
    __half*   rech_p = (__half*)(base + U_RECH_P);
    __half*   rech_d = (__half*)(base + U_RECH_D);
    __half*   wcomb  = (__half*)(base + U_WCOMB);
    __half*   wrpp   = (__half*)(base + U_WRPP);
    __half*   wrdp   = (__half*)(base + U_WRDP);
    __half*   wrpd   = (__half*)(base + U_WRPD);
    __half*   wlpd   = (__half*)(base + U_WLPD);
    __half*   wdecp  = (__half*)(base + U_WDECP);
    __half*   wdecd  = (__half*)(base + U_WDECD);
    float*    bsum   = (float*)(base + U_BSUM);

    cudaFuncSetAttribute(gemm_enc, cudaFuncAttributeMaxDynamicSharedMemorySize,
                         E_SMEM);
    cudaFuncSetAttribute(gemm_h, cudaFuncAttributeMaxDynamicSharedMemorySize,
                         GEMM_SMEM);

    // k1: zero + weight prep + x -> half (plain + normalized)
    PrepArgs pa;
    pa.wlpp = Wl_pp; pa.wldp = Wl_dp; pa.wrpp = Wr_pp; pa.wrdp = Wr_dp;
    pa.wrpd = Wr_pd; pa.wlpd = Wl_pd; pa.wdecp = Wdec_p; pa.wdecd = Wdec_d;
    pa.bpp = b_pp; pa.bdp = b_dp;
    pa.o_wcomb = (unsigned*)wcomb; pa.o_wrpp = (unsigned*)wrpp;
    pa.o_wrdp = (unsigned*)wrdp; pa.o_wrpd = (unsigned*)wrpd;
    pa.o_wlpd = (unsigned*)wlpd; pa.o_wdecp = (unsigned*)wdecp;
    pa.o_wdecd = (unsigned*)wdecd; pa.o_bsum = bsum;
    pa.xin[0] = x_paper;   pa.xout_p[0] = (uint2*)xh_p; pa.xout_n[0] = (uint2*)xnh_p; pa.xrows[0] = NP;
    pa.xin[1] = x_dataset; pa.xout_p[1] = (uint2*)xh_d; pa.xout_n[1] = (uint2*)xnh_d; pa.xrows[1] = ND;
    pa.zbase = (float4*)base; pa.zn4 = ZERO_END / 4;
    pa.nW = (unsigned)((FD * FD + 255) / 256);
    pa.nX = (unsigned)(((size_t)(NP + ND) * 32 + 255) / 256);
    zero_prep<<<pa.nW + pa.nX + 4096, 256>>>(pa);

    // k2: scatter (gathers half x)
    ScatArgs sa;
    sa.ei[0] = ei_pp; sa.x[0] = xh_p; sa.sum[0] = sum_pp; sa.cnt[0] = cnt_pp; sa.E[0] = Epp;
    sa.ei[1] = ei_dp; sa.x[1] = xh_d; sa.sum[1] = sum_dp; sa.cnt[1] = cnt_dp; sa.E[1] = Edp;
    sa.ei[2] = ei_pd; sa.x[2] = xh_p; sa.sum[2] = sum_pd; sa.cnt[2] = cnt_pd; sa.E[2] = Epd;
    int nb0 = (Epp + 3) / 4, nb1 = (Edp + 3) / 4, nb2 = (Epd + 3) / 4;
    sa.b0 = nb0; sa.b01 = nb0 + nb1;
    scatter_all<<<nb0 + nb1 + nb2, 256>>>(sa);

    // k3: finalize means -> half (vectorized, 8 elems/thread)
    FinArgs fa;
    fa.sum[0] = (const float4*)sum_pp; fa.cnt[0] = cnt_pp; fa.outh[0] = (uint4*)mh_pp; fa.n[0] = (size_t)NP * 64;
    fa.sum[1] = (const float4*)sum_dp; fa.cnt[1] = cnt_dp; fa.outh[1] = (uint4*)mh_dp; fa.n[1] = (size_t)NP * 64;
    fa.sum[2] = (const float4*)sum_pd; fa.cnt[2] = cnt_pd; fa.outh[2] = (uint4*)mh_pd; fa.n[2] = (size_t)ND * 64;
    size_t ftot = fa.n[0] + fa.n[1] + fa.n[2];
    finalize_all<<<(int)((ftot + 255) / 256), 256>>>(fa);

    // k4: encoder GEMMs, fused L2-norm epilogue -> rech (half)
    const int gpe = (NP + 63) / 64;   // 782
    const int gde = (ND + 63) / 64;   // 79
    ProbE e0 = {}, e1 = {};
    e0.segs.A[0] = mh_pp; e0.segs.B[0] = wrpp;  e0.segs.ldb[0] = FD;
    e0.segs.A[1] = mh_dp; e0.segs.B[1] = wrdp;  e0.segs.ldb[1] = FD;
    e0.segs.A[2] = xh_p;  e0.segs.B[2] = wcomb; e0.segs.ldb[2] = FD;
    e0.nseg = 3; e0.bias = bsum; e0.Ch = rech_p; e0.M = NP;
    e1.segs.A[0] = mh_pd; e1.segs.B[0] = wrpd; e1.segs.ldb[0] = FD;
    e1.segs.A[1] = xh_d;  e1.segs.B[1] = wlpd; e1.segs.ldb[1] = FD;
    e1.nseg = 2; e1.bias = b_pd; e1.Ch = rech_d; e1.M = ND;
    gemm_enc<<<gpe + gde, 256, E_SMEM>>>(e0, e1, gpe);

    // k5: decoder GEMMs -> out (fp32)
    const int gp = (NP + 127) / 128;
    const int gd = (ND + 127) / 128;
    dim3 ggrid(gp + gd, FD / 256);
    ProbH d0 = {}, d1 = {};
    d0.segs.A[0] = rech_p; d0.segs.B[0] = wdecp;      d0.segs.ldb[0] = 2 * FD;
    d0.segs.A[1] = xnh_p;  d0.segs.B[1] = wdecp + FD; d0.segs.ldb[1] = 2 * FD;
    d0.nseg = 2; d0.bias = bdec_p; d0.C = out; d0.M = NP;
    d1.segs.A[0] = rech_d; d1.segs.B[0] = wdecd;      d1.segs.ldb[0] = 2 * FD;
    d1.segs.A[1] = xnh_d;  d1.segs.B[1] = wdecd + FD; d1.segs.ldb[1] = 2 * FD;
    d1.nseg = 2; d1.bias = bdec_d; d1.C = out + (size_t)NP * FD; d1.M = ND;
    gemm_h<<<ggrid, NTHR, GEMM_SMEM>>>(d0, d1, gp);
}

// round 15
// speedup vs baseline: 1.2273x; 1.1351x over previous
#include <cuda_runtime.h>
#include <cuda_fp16.h>
#include <math.h>
#include <stdint.h>

#define NP 50000
#define ND 5000
#define FD 512

// ---------------------------------------------------------------------------
// Scratch (u32 units)
// ---------------------------------------------------------------------------
constexpr size_t NPF   = (size_t)NP * FD;
constexpr size_t NDF   = (size_t)ND * FD;
constexpr size_t U_SUM_PP = 0;
constexpr size_t U_SUM_DP = U_SUM_PP + NPF;
constexpr size_t U_SUM_PD = U_SUM_DP + NPF;
constexpr size_t U_CNT_PP = U_SUM_PD + NDF;
constexpr size_t U_CNT_DP = U_CNT_PP + NP;
constexpr size_t U_CNT_PD = U_CNT_DP + NP;
constexpr size_t ZERO_END = U_CNT_PD + ND;
constexpr size_t U_MH_PP  = (ZERO_END + 1) & ~(size_t)1;
constexpr size_t U_MH_DP  = U_MH_PP + NPF / 2;
constexpr size_t U_MH_PD  = U_MH_DP + NPF / 2;
constexpr size_t U_XH_P   = U_MH_PD + NDF / 2;     // half x (plain)
constexpr size_t U_XH_D   = U_XH_P + NPF / 2;
constexpr size_t U_XNH_P  = U_XH_D + NDF / 2;      // half x (normalized)
constexpr size_t U_XNH_D  = U_XNH_P + NPF / 2;
constexpr size_t U_RECH_P = U_XNH_D + NDF / 2;     // half rec (normalized)
constexpr size_t U_RECH_D = U_RECH_P + NPF / 2;
constexpr size_t U_WCOMB  = U_RECH_D + NDF / 2;
constexpr size_t U_WRPP   = U_WCOMB + (size_t)FD * FD / 2;
constexpr size_t U_WRDP   = U_WRPP + (size_t)FD * FD / 2;
constexpr size_t U_WRPD   = U_WRDP + (size_t)FD * FD / 2;
constexpr size_t U_WLPD   = U_WRPD + (size_t)FD * FD / 2;
constexpr size_t U_WDECP  = U_WLPD + (size_t)FD * FD / 2;
constexpr size_t U_WDECD  = U_WDECP + (size_t)FD * FD;
constexpr size_t U_BSUM   = U_WDECD + (size_t)FD * FD;
constexpr size_t U_TOTAL  = U_BSUM + FD;

__device__ __align__(16) unsigned g_scratch[U_TOTAL];

__device__ __forceinline__ unsigned pack_h2(float a, float b) {
    __half2 h = __floats2half2_rn(a, b);
    return *reinterpret_cast<unsigned*>(&h);
}

// ---------------------------------------------------------------------------
// k1: zero sums+counts
// ---------------------------------------------------------------------------
__global__ void zero_k(float4* p, size_t n4) {
    size_t i = (size_t)blockIdx.x * blockDim.x + threadIdx.x;
    size_t stride = (size_t)gridDim.x * blockDim.x;
    for (; i < n4; i += stride) p[i] = make_float4(0.f, 0.f, 0.f, 0.f);
}

// ---------------------------------------------------------------------------
// k2: weight prep (half) + bias sum
// ---------------------------------------------------------------------------
struct WArgs {
    const float *wlpp, *wldp, *wrpp, *wrdp, *wrpd, *wlpd, *wdecp, *wdecd, *bpp, *bdp;
    unsigned *o_wcomb, *o_wrpp, *o_wrdp, *o_wrpd, *o_wlpd, *o_wdecp, *o_wdecd;
    float* o_bsum;
};

__global__ void wprep_k(WArgs a) {
    int idx = blockIdx.x * blockDim.x + threadIdx.x;
    const int nh = FD * FD / 2;
    if (idx < nh) {
        int j = 2 * idx;
        a.o_wcomb[idx] = pack_h2(a.wlpp[j] + a.wldp[j], a.wlpp[j + 1] + a.wldp[j + 1]);
        a.o_wrpp[idx]  = pack_h2(a.wrpp[j], a.wrpp[j + 1]);
        a.o_wrdp[idx]  = pack_h2(a.wrdp[j], a.wrdp[j + 1]);
        a.o_wrpd[idx]  = pack_h2(a.wrpd[j], a.wrpd[j + 1]);
        a.o_wlpd[idx]  = pack_h2(a.wlpd[j], a.wlpd[j + 1]);
    }
    if (idx < 2 * nh) {
        int j = 2 * idx;
        a.o_wdecp[idx] = pack_h2(a.wdecp[j], a.wdecp[j + 1]);
        a.o_wdecd[idx] = pack_h2(a.wdecd[j], a.wdecd[j + 1]);
    }
    if (idx < FD) a.o_bsum[idx] = a.bpp[idx] + a.bdp[idx];
}

// ---------------------------------------------------------------------------
// k3: x -> half (plain + l2-normalized), warp per row
// ---------------------------------------------------------------------------
struct XArgs {
    const float* xin[2];
    uint2* xout_p[2];
    uint2* xout_n[2];
    int xrows[2];
};

__global__ void xnorm_k(XArgs a) {
    int row = (int)(((size_t)blockIdx.x * blockDim.x + threadIdx.x) >> 5);
    int t = 0;
    if (row >= a.xrows[0]) { row -= a.xrows[0]; t = 1; }
    if (t == 1 && row >= a.xrows[1]) return;
    int lane = threadIdx.x & 31;
    const float4* p = (const float4*)(a.xin[t] + (size_t)row * FD);
    float4 v[4];
    float ss = 0.f;
#pragma unroll
    for (int i = 0; i < 4; i++) {
        v[i] = p[lane + 32 * i];
        ss += v[i].x * v[i].x + v[i].y * v[i].y + v[i].z * v[i].z + v[i].w * v[i].w;
    }
#pragma unroll
    for (int o = 16; o > 0; o >>= 1) ss += __shfl_xor_sync(0xffffffffu, ss, o);
    float inv = 1.0f / fmaxf(sqrtf(ss), 1e-12f);
    uint2* qp = a.xout_p[t] + (size_t)row * 128;
    uint2* qn = a.xout_n[t] + (size_t)row * 128;
#pragma unroll
    for (int i = 0; i < 4; i++) {
        qp[lane + 32 * i] = make_uint2(pack_h2(v[i].x, v[i].y),
                                       pack_h2(v[i].z, v[i].w));
        qn[lane + 32 * i] = make_uint2(pack_h2(v[i].x * inv, v[i].y * inv),
                                       pack_h2(v[i].z * inv, v[i].w * inv));
    }
}

// ---------------------------------------------------------------------------
// k4: scatter — 64 lanes/group, 4 groups/block, 4 edges batched per group
// (MLP=4 on gathers). Gather half x, fp32 red.
// ---------------------------------------------------------------------------
struct ScatArgs {
    const int* ei[3];
    const __half* x[3];
    float* sum[3];
    float* cnt[3];
    int E[3];
    int b0, b01;
};

__global__ void scatter_all(ScatArgs a) {
    int b = blockIdx.x, t;
    if (b < a.b0)       { t = 0; }
    else if (b < a.b01) { t = 1; b -= a.b0; }
    else                { t = 2; b -= a.b01; }
    const int grp  = threadIdx.x >> 6;       // 0..3
    const int lane = threadIdx.x & 63;
    const int E = a.E[t];
    const int e0 = (b * 4 + grp) * 4;
    if (e0 >= E) return;
    const int* ei = a.ei[t];
    const __half* x = a.x[t];

    int src[4], dst[4];
    bool ok[4];
#pragma unroll
    for (int i = 0; i < 4; i++) {
        int e = e0 + i;
        ok[i] = e < E;
        src[i] = ok[i] ? ei[e] : 0;
        dst[i] = ok[i] ? ei[(size_t)E + e] : 0;
    }
    uint4 hv[4];
#pragma unroll
    for (int i = 0; i < 4; i++)
        hv[i] = *(const uint4*)(x + (size_t)src[i] * FD + lane * 8);

#pragma unroll
    for (int i = 0; i < 4; i++) {
        if (!ok[i]) continue;
        float2 f0 = __half22float2(*(__half2*)&hv[i].x);
        float2 f1 = __half22float2(*(__half2*)&hv[i].y);
        float2 f2 = __half22float2(*(__half2*)&hv[i].z);
        float2 f3 = __half22float2(*(__half2*)&hv[i].w);
        float* o = a.sum[t] + (size_t)dst[i] * FD + lane * 8;
        asm volatile("red.global.add.v4.f32 [%0], {%1,%2,%3,%4};"
                     :: "l"(o), "f"(f0.x), "f"(f0.y), "f"(f1.x), "f"(f1.y) : "memory");
        asm volatile("red.global.add.v4.f32 [%0], {%1,%2,%3,%4};"
                     :: "l"(o + 4), "f"(f2.x), "f"(f2.y), "f"(f3.x), "f"(f3.y) : "memory");
        if (lane == 0) atomicAdd(a.cnt[t] + dst[i], 1.0f);
    }
}

// ---------------------------------------------------------------------------
// k5: finalize means -> half, vectorized: 1 uint4 out (8 elems) per thread
// ---------------------------------------------------------------------------
struct FinArgs {
    const float4* sum[3];
    const float* cnt[3];
    uint4* outh[3];
    size_t n[3];       // uint4 jobs per region (= rows * 64)
};

__global__ void finalize_all(FinArgs a) {
    size_t i = (size_t)blockIdx.x * blockDim.x + threadIdx.x;
    int t = 0;
    if (i >= a.n[0]) { i -= a.n[0]; t = 1; }
    if (t == 1 && i >= a.n[1]) { i -= a.n[1]; t = 2; }
    if (t == 2 && i >= a.n[2]) return;
    int row = (int)(i >> 6);                  // 64 uint4 per row
    float iv = 1.0f / fmaxf(a.cnt[t][row], 1.0f);
    const float4* s = a.sum[t] + 2 * i;
    float4 v0 = s[0];
    float4 v1 = s[1];
    a.outh[t][i] = make_uint4(pack_h2(v0.x * iv, v0.y * iv),
                              pack_h2(v0.z * iv, v0.w * iv),
                              pack_h2(v1.x * iv, v1.y * iv),
                              pack_h2(v1.z * iv, v1.w * iv));
}

// ---------------------------------------------------------------------------
// shared GEMM helpers
// ---------------------------------------------------------------------------
struct SegH {
    const __half* A[3];
    const __half* B[3];
    int ldb[3];
};

#define SROW_H 40

__device__ __forceinline__ void cp16s(uint32_t dst_smem, const void* src) {
    asm volatile("cp.async.cg.shared.global [%0], [%1], 16;"
                 :: "r"(dst_smem), "l"(src));
}
__device__ __forceinline__ uint32_t smem_u32(const void* p) {
    uint32_t a;
    asm("{ .reg .u64 t; cvta.to.shared.u64 t, %1; cvt.u32.u64 %0, t; }"
        : "=r"(a) : "l"(p));
    return a;
}
#define LDMX4(r0, r1, r2, r3, addr) \
    asm volatile("ldmatrix.sync.aligned.m8n8.x4.shared.b16 {%0,%1,%2,%3}, [%4];" \
                 : "=r"(r0), "=r"(r1), "=r"(r2), "=r"(r3) : "r"(addr))
#define MMA16816(acc, av, bv) \
    asm volatile( \
        "mma.sync.aligned.m16n8k16.row.col.f32.f16.f16.f32 " \
        "{%0,%1,%2,%3}, {%4,%5,%6,%7}, {%8,%9}, {%0,%1,%2,%3};" \
        : "+f"((acc)[0]), "+f"((acc)[1]), "+f"((acc)[2]), "+f"((acc)[3]) \
        : "r"((av)[0]), "r"((av)[1]), "r"((av)[2]), "r"((av)[3]), \
          "r"((bv)[0]), "r"((bv)[1]))

extern __shared__ __align__(128) unsigned char hsm[];

// ---------------------------------------------------------------------------
// Encoder GEMM (R11/R14 config): BM=64 x BN=512(full) x BK=32, 256 thr /
// 8 warps (1x8), warp tile 64x64, 4-stage cp.async.
// Epilogue: +bias, full-row L2 norm, write half normalized.
// ---------------------------------------------------------------------------
struct ProbE {
    SegH segs;
    int nseg;
    const float* bias;
    __half* Ch;
    int M;
};

#define E_ASTG (64 * SROW_H * 2)          // 5120
#define E_BSTG (512 * SROW_H * 2)         // 40960
#define E_STG  (E_ASTG + E_BSTG)          // 46080
#define E_SMEM (4 * E_STG)                // 184320

__global__ __launch_bounds__(256, 1) void gemm_enc(ProbE p0, ProbE p1, int split) {
    const bool first = (blockIdx.x < (unsigned)split);
    ProbE p = first ? p0 : p1;
    const int bm = (first ? blockIdx.x : blockIdx.x - split) * 64;

    const int tid  = threadIdx.x;
    const int lane = tid & 31;
    const int wn   = tid >> 5;           // 0..7
    const int g    = lane >> 2;
    const int t4   = lane & 3;

    const uint32_t dyn = smem_u32(hsm);
    __shared__ float rowss[64];

    const uint32_t aoff =
        (uint32_t)(((lane & 15) * SROW_H + ((lane >> 4) << 3)) * 2);
    const uint32_t boff = E_ASTG +
        (uint32_t)(((wn * 64 + (lane & 7) + (((lane >> 4) & 1) << 3)) * SROW_H +
                    (((lane >> 3) & 1) << 3)) * 2);

    float acc[4][8][4];
#pragma unroll
    for (int mi = 0; mi < 4; mi++)
#pragma unroll
        for (int ni = 0; ni < 8; ni++)
#pragma unroll
            for (int r = 0; r < 4; r++) acc[mi][ni][r] = 0.f;

    const int NKB = p.nseg * (FD / 32);

    auto issue = [&](int kb) {
        const int st   = kb & 3;
        const int s    = kb >> 4;
        const int koff = (kb & 15) * 32;
        const uint32_t abase = dyn + st * E_STG;
        const uint32_t bbase = abase + E_ASTG;
        {   // A: 64 rows x 4 c16 = 256 jobs (1/thread)
            int row = tid >> 2, c16 = tid & 3;
            int r = bm + row;
            if (r < p.M)
                cp16s(abase + (uint32_t)(row * (SROW_H * 2) + c16 * 16),
                      p.segs.A[s] + (size_t)r * FD + koff + c16 * 8);
            else {
                uint32_t d = abase + (uint32_t)(row * (SROW_H * 2) + c16 * 16);
                asm volatile("st.shared.v4.u32 [%0], {%1,%1,%1,%1};"
                             :: "r"(d), "r"(0u));
            }
        }
        const __half* Bb = p.segs.B[s];
        const int ldb = p.segs.ldb[s];
#pragma unroll
        for (int i = 0; i < 8; i++) {    // B: 512 rows x 4 = 2048 jobs (8/thread)
            int u = tid + i * 256;
            int row = u >> 2, c16 = u & 3;
            cp16s(bbase + (uint32_t)(row * (SROW_H * 2) + c16 * 16),
                  Bb + (size_t)row * ldb + koff + c16 * 8);
        }
        asm volatile("cp.async.commit_group;");
    };

    issue(0);
    if (NKB > 1) issue(1);
    if (NKB > 2) issue(2);

    for (int c = 0; c < NKB; c++) {
        const int st = c & 3;
        if (c + 3 < NKB) issue(c + 3);
        const int rem = NKB - 1 - c;
        if (rem >= 3)      asm volatile("cp.async.wait_group 3;");
        else if (rem == 2) asm volatile("cp.async.wait_group 2;");
        else if (rem == 1) asm volatile("cp.async.wait_group 1;");
        else               asm volatile("cp.async.wait_group 0;");
        __syncthreads();

        const uint32_t stBase = dyn + st * E_STG;
#pragma unroll
        for (int ks = 0; ks < 2; ks++) {
            unsigned a[4][4], b[8][2];
#pragma unroll
            for (int mi = 0; mi < 4; mi++)
                LDMX4(a[mi][0], a[mi][1], a[mi][2], a[mi][3],
                      stBase + aoff + (uint32_t)(mi * 16 * SROW_H * 2 + ks * 32));
#pragma unroll
            for (int pi = 0; pi < 4; pi++)
                LDMX4(b[2 * pi][0], b[2 * pi][1], b[2 * pi + 1][0], b[2 * pi + 1][1],
                      stBase + boff + (uint32_t)(pi * 16 * SROW_H * 2 + ks * 32));
#pragma unroll
            for (int mi = 0; mi < 4; mi++)
#pragma unroll
                for (int ni = 0; ni < 8; ni++)
                    MMA16816(acc[mi][ni], a[mi], b[ni]);
        }
        __syncthreads();
    }

    // epilogue: +bias, row ssq over full 512 cols, normalize, write half
    float bb[8][2];
#pragma unroll
    for (int ni = 0; ni < 8; ni++) {
        int c = wn * 64 + ni * 8 + t4 * 2;
        bb[ni][0] = p.bias[c];
        bb[ni][1] = p.bias[c + 1];
    }
    if (tid < 64) rowss[tid] = 0.f;
    __syncthreads();
#pragma unroll
    for (int mi = 0; mi < 4; mi++) {
        float s0 = 0.f, s1 = 0.f;
#pragma unroll
        for (int ni = 0; ni < 8; ni++) {
            float v0 = acc[mi][ni][0] + bb[ni][0];
            float v1 = acc[mi][ni][1] + bb[ni][1];
            float v2 = acc[mi][ni][2] + bb[ni][0];
            float v3 = acc[mi][ni][3] + bb[ni][1];
            acc[mi][ni][0] = v0; acc[mi][ni][1] = v1;
            acc[mi][ni][2] = v2; acc[mi][ni][3] = v3;
            s0 += v0 * v0 + v1 * v1;
            s1 += v2 * v2 + v3 * v3;
        }
        s0 += __shfl_xor_sync(0xffffffffu, s0, 1);
        s0 += __shfl_xor_sync(0xffffffffu, s0, 2);
        s1 += __shfl_xor_sync(0xffffffffu, s1, 1);
        s1 += __shfl_xor_sync(0xffffffffu, s1, 2);
        if (t4 == 0) {
            atomicAdd(&rowss[mi * 16 + g], s0);
            atomicAdd(&rowss[mi * 16 + g + 8], s1);
        }
    }
    __syncthreads();
#pragma unroll
    for (int mi = 0; mi < 4; mi++) {
        const int r0 = mi * 16 + g;
        const int gr0 = bm + r0;
        const float inv0 = 1.0f / fmaxf(sqrtf(rowss[r0]), 1e-12f);
        const float inv1 = 1.0f / fmaxf(sqrtf(rowss[r0 + 8]), 1e-12f);
#pragma unroll
        for (int ni = 0; ni < 8; ni++) {
            const int c = wn * 64 + ni * 8 + t4 * 2;
            if (gr0 < p.M)
                *(unsigned*)(p.Ch + (size_t)gr0 * FD + c) =
                    pack_h2(acc[mi][ni][0] * inv0, acc[mi][ni][1] * inv0);
            if (gr0 + 8 < p.M)
                *(unsigned*)(p.Ch + (size_t)(gr0 + 8) * FD + c) =
                    pack_h2(acc[mi][ni][2] * inv1, acc[mi][ni][3] * inv1);
        }
    }
}

// ---------------------------------------------------------------------------
// Decoder GEMM: 128x256x32, 512 thr / 16 warps, warp 64x32.
// ---------------------------------------------------------------------------
struct ProbH {
    SegH segs;
    int nseg;
    const float* bias;
    float* C;
    int M;
};

#define NTHR 512
#define A_BYTES_H (128 * SROW_H * 2)
#define B_BYTES_H (256 * SROW_H * 2)
#define STG_H (A_BYTES_H + B_BYTES_H)
#define GEMM_SMEM (4 * STG_H)

__global__ __launch_bounds__(NTHR, 1) void gemm_h(ProbH p0, ProbH p1, int split) {
    const bool first = (blockIdx.x < (unsigned)split);
    ProbH p = first ? p0 : p1;
    const int bm = (first ? blockIdx.x : blockIdx.x - split) * 128;
    const int bn = blockIdx.y * 256;

    const int tid  = threadIdx.x;
    const int lane = tid & 31;
    const int warp = tid >> 5;
    const int wm = warp >> 3;
    const int wn = warp & 7;
    const int g  = lane >> 2;
    const int t4 = lane & 3;

    const uint32_t dyn = smem_u32(hsm);

    const uint32_t aoff =
        (uint32_t)(((wm * 64 + (lane & 15)) * SROW_H + ((lane >> 4) << 3)) * 2);
    const uint32_t boff = A_BYTES_H +
        (uint32_t)(((wn * 32 + (lane & 7) + (((lane >> 4) & 1) << 3)) * SROW_H +
                    (((lane >> 3) & 1) << 3)) * 2);

    float acc[4][4][4];
#pragma unroll
    for (int mi = 0; mi < 4; mi++)
#pragma unroll
        for (int ni = 0; ni < 4; ni++)
#pragma unroll
            for (int r = 0; r < 4; r++) acc[mi][ni][r] = 0.f;

    const int NKB = p.nseg * (FD / 32);

    auto issue = [&](int kb) {
        const int st   = kb & 3;
        const int s    = kb >> 4;
        const int koff = (kb & 15) * 32;
        const uint32_t abase = dyn + st * STG_H;
        const uint32_t bbase = abase + A_BYTES_H;
        {
            int row = tid >> 2, c16 = tid & 3;
            int r = bm + row;
            if (r < p.M)
                cp16s(abase + (uint32_t)(row * (SROW_H * 2) + c16 * 16),
                      p.segs.A[s] + (size_t)r * FD + koff + c16 * 8);
            else {
                uint32_t d = abase + (uint32_t)(row * (SROW_H * 2) + c16 * 16);
                asm volatile("st.shared.v4.u32 [%0], {%1,%1,%1,%1};"
                             :: "r"(d), "r"(0u));
            }
        }
        const __half* Bb = p.segs.B[s];
        const int ldb = p.segs.ldb[s];
#pragma unroll
        for (int i = 0; i < 2; i++) {
            int u = tid + i * NTHR;
            int row = u >> 2, c16 = u & 3;
            cp16s(bbase + (uint32_t)(row * (SROW_H * 2) + c16 * 16),
                  Bb + (size_t)(bn + row) * ldb + koff + c16 * 8);
        }
        asm volatile("cp.async.commit_group;");
    };

    issue(0);
    if (NKB > 1) issue(1);
    if (NKB > 2) issue(2);

    for (int c = 0; c < NKB; c++) {
        const int st = c & 3;
        if (c + 3 < NKB) issue(c + 3);
        const int rem = NKB - 1 - c;
        if (rem >= 3)      asm volatile("cp.async.wait_group 3;");
        else if (rem == 2) asm volatile("cp.async.wait_group 2;");
        else if (rem == 1) asm volatile("cp.async.wait_group 1;");
        else               asm volatile("cp.async.wait_group 0;");
        __syncthreads();

        const uint32_t stBase = dyn + st * STG_H;
#pragma unroll
        for (int ks = 0; ks < 2; ks++) {
            unsigned a[4][4], b[4][2];
#pragma unroll
            for (int mi = 0; mi < 4; mi++)
                LDMX4(a[mi][0], a[mi][1], a[mi][2], a[mi][3],
                      stBase + aoff + (uint32_t)(mi * 16 * SROW_H * 2 + ks * 32));
#pragma unroll
            for (int pi = 0; pi < 2; pi++)
                LDMX4(b[2 * pi][0], b[2 * pi][1], b[2 * pi + 1][0], b[2 * pi + 1][1],
                      stBase + boff + (uint32_t)(pi * 16 * SROW_H * 2 + ks * 32));
#pragma unroll
            for (int mi = 0; mi < 4; mi++)
#pragma unroll
                for (int ni = 0; ni < 4; ni++)
                    MMA16816(acc[mi][ni], a[mi], b[ni]);
        }
        __syncthreads();
    }

#pragma unroll
    for (int ni = 0; ni < 4; ni++) {
        const int c = bn + wn * 32 + ni * 8 + t4 * 2;
        const float bb0 = p.bias[c];
        const float bb1 = p.bias[c + 1];
#pragma unroll
        for (int mi = 0; mi < 4; mi++) {
            const int r0 = bm + wm * 64 + mi * 16 + g;
            if (r0 < p.M)
                *(float2*)(p.C + (size_t)r0 * FD + c) =
                    make_float2(acc[mi][ni][0] + bb0, acc[mi][ni][1] + bb1);
            const int r1 = r0 + 8;
            if (r1 < p.M)
                *(float2*)(p.C + (size_t)r1 * FD + c) =
                    make_float2(acc[mi][ni][2] + bb0, acc[mi][ni][3] + bb1);
        }
    }
}

// ---------------------------------------------------------------------------
// kernel_launch — 7 launches; #4 = scatter (ncu lands there)
// ---------------------------------------------------------------------------
extern "C" void kernel_launch(void* const* d_in, const int* in_sizes, int n_in,
                              void* d_out, int out_size) {
    const float* x_paper   = (const float*)d_in[0];
    const float* x_dataset = (const float*)d_in[1];
    const int*   ei_pp     = (const int*)d_in[2];
    const int*   ei_pd     = (const int*)d_in[3];
    const int*   ei_dp     = (const int*)d_in[4];
    const float* Wl_pp = (const float*)d_in[5];
    const float* Wr_pp = (const float*)d_in[6];
    const float* b_pp  = (const float*)d_in[7];
    const float* Wl_pd = (const float*)d_in[8];
    const float* Wr_pd = (const float*)d_in[9];
    const float* b_pd  = (const float*)d_in[10];
    const float* Wl_dp = (const float*)d_in[11];
    const float* Wr_dp = (const float*)d_in[12];
    const float* b_dp  = (const float*)d_in[13];
    const float* Wdec_p = (const float*)d_in[14];
    const float* bdec_p = (const float*)d_in[15];
    const float* Wdec_d = (const float*)d_in[16];
    const float* bdec_d = (const float*)d_in[17];

    const int Epp = in_sizes[2] / 2;
    const int Epd = in_sizes[3] / 2;
    const int Edp = in_sizes[4] / 2;

    float* out = (float*)d_out;

    unsigned* base = nullptr;
    cudaGetSymbolAddress((void**)&base, g_scratch);
    float*    sum_pp = (float*)(base + U_SUM_PP);
    float*    sum_dp = (float*)(base + U_SUM_DP);
    float*    sum_pd = (float*)(base + U_SUM_PD);
    float*    cnt_pp = (float*)(base + U_CNT_PP);
    float*    cnt_dp = (float*)(base + U_CNT_DP);
    float*    cnt_pd = (float*)(base + U_CNT_PD);
    __half*   mh_pp  = (__half*)(base + U_MH_PP);
    __half*   mh_dp  = (__half*)(base + U_MH_DP);
    __half*   mh_pd  = (__half*)(base + U_MH_PD);
    __half*   xh_p   = (__half*)(base + U_XH_P);
    __half*   xh_d   = (__half*)(base + U_XH_D);
    __half*   xnh_p  = (__half*)(base + U_XNH_P);
    __half*   xnh_d  = (__half*)(base + U_XNH_D);
    __half*   rech_p = (__half*)(base + U_RECH_P);
    __half*   rech_d = (__half*)(base + U_RECH_D);
    __half*   wcomb  = (__half*)(base + U_WCOMB);
    __half*   wrpp   = (__half*)(base + U_WRPP);
    __half*   wrdp   = (__half*)(base + U_WRDP);
    __half*   wrpd   = (__half*)(base + U_WRPD);
    __half*   wlpd   = (__half*)(base + U_WLPD);
    __half*   wdecp  = (__half*)(base + U_WDECP);
    __half*   wdecd  = (__half*)(base + U_WDECD);
    float*    bsum   = (float*)(base + U_BSUM);

    cudaFuncSetAttribute(gemm_enc, cudaFuncAttributeMaxDynamicSharedMemorySize,
                         E_SMEM);
    cudaFuncSetAttribute(gemm_h, cudaFuncAttributeMaxDynamicSharedMemorySize,
                         GEMM_SMEM);

    // k1: zero sums + counts
    zero_k<<<4096, 256>>>((float4*)base, ZERO_END / 4);

    // k2: weight prep
    WArgs wa;
    wa.wlpp = Wl_pp; wa.wldp = Wl_dp; wa.wrpp = Wr_pp; wa.wrdp = Wr_dp;
    wa.wrpd = Wr_pd; wa.wlpd = Wl_pd; wa.wdecp = Wdec_p; wa.wdecd = Wdec_d;
    wa.bpp = b_pp; wa.bdp = b_dp;
    wa.o_wcomb = (unsigned*)wcomb; wa.o_wrpp = (unsigned*)wrpp;
    wa.o_wrdp = (unsigned*)wrdp; wa.o_wrpd = (unsigned*)wrpd;
    wa.o_wlpd = (unsigned*)wlpd; wa.o_wdecp = (unsigned*)wdecp;
    wa.o_wdecd = (unsigned*)wdecd; wa.o_bsum = bsum;
    wprep_k<<<(FD * FD + 255) / 256, 256>>>(wa);

    // k3: x -> half (plain + normalized)
    XArgs xa;
    xa.xin[0] = x_paper;   xa.xout_p[0] = (uint2*)xh_p; xa.xout_n[0] = (uint2*)xnh_p; xa.xrows[0] = NP;
    xa.xin[1] = x_dataset; xa.xout_p[1] = (uint2*)xh_d; xa.xout_n[1] = (uint2*)xnh_d; xa.xrows[1] = ND;
    xnorm_k<<<((NP + ND) * 32 + 255) / 256, 256>>>(xa);

    // k4: scatter (batched, MLP=4) — ncu profile target
    ScatArgs sa;
    sa.ei[0] = ei_pp; sa.x[0] = xh_p; sa.sum[0] = sum_pp; sa.cnt[0] = cnt_pp; sa.E[0] = Epp;
    sa.ei[1] = ei_dp; sa.x[1] = xh_d; sa.sum[1] = sum_dp; sa.cnt[1] = cnt_dp; sa.E[1] = Edp;
    sa.ei[2] = ei_pd; sa.x[2] = xh_p; sa.sum[2] = sum_pd; sa.cnt[2] = cnt_pd; sa.E[2] = Epd;
    int nb0 = (Epp + 15) / 16, nb1 = (Edp + 15) / 16, nb2 = (Epd + 15) / 16;
    sa.b0 = nb0; sa.b01 = nb0 + nb1;
    scatter_all<<<nb0 + nb1 + nb2, 256>>>(sa);

    // k5: finalize means -> half (vectorized)
    FinArgs fa;
    fa.sum[0] = (const float4*)sum_pp; fa.cnt[0] = cnt_pp; fa.outh[0] = (uint4*)mh_pp; fa.n[0] = (size_t)NP * 64;
    fa.sum[1] = (const float4*)sum_dp; fa.cnt[1] = cnt_dp; fa.outh[1] = (uint4*)mh_dp; fa.n[1] = (size_t)NP * 64;
    fa.sum[2] = (const float4*)sum_pd; fa.cnt[2] = cnt_pd; fa.outh[2] = (uint4*)mh_pd; fa.n[2] = (size_t)ND * 64;
    size_t ftot = fa.n[0] + fa.n[1] + fa.n[2];
    finalize_all<<<(int)((ftot + 255) / 256), 256>>>(fa);

    // k6: encoder GEMMs, fused L2-norm epilogue -> rech (half)
    const int gpe = (NP + 63) / 64;   // 782
    const int gde = (ND + 63) / 64;   // 79
    ProbE e0 = {}, e1 = {};
    e0.segs.A[0] = mh_pp; e0.segs.B[0] = wrpp;  e0.segs.ldb[0] = FD;
    e0.segs.A[1] = mh_dp; e0.segs.B[1] = wrdp;  e0.segs.ldb[1] = FD;
    e0.segs.A[2] = xh_p;  e0.segs.B[2] = wcomb; e0.segs.ldb[2] = FD;
    e0.nseg = 3; e0.bias = bsum; e0.Ch = rech_p; e0.M = NP;
    e1.segs.A[0] = mh_pd; e1.segs.B[0] = wrpd; e1.segs.ldb[0] = FD;
    e1.segs.A[1] = xh_d;  e1.segs.B[1] = wlpd; e1.segs.ldb[1] = FD;
    e1.nseg = 2; e1.bias = b_pd; e1.Ch = rech_d; e1.M = ND;
    gemm_enc<<<gpe + gde, 256, E_SMEM>>>(e0, e1, gpe);

    // k7: decoder GEMMs -> out (fp32)
    const int gp = (NP + 127) / 128;
    const int gd = (ND + 127) / 128;
    dim3 ggrid(gp + gd, FD / 256);
    ProbH d0 = {}, d1 = {};
    d0.segs.A[0] = rech_p; d0.segs.B[0] = wdecp;      d0.segs.ldb[0] = 2 * FD;
    d0.segs.A[1] = xnh_p;  d0.segs.B[1] = wdecp + FD; d0.segs.ldb[1] = 2 * FD;
    d0.nseg = 2; d0.bias = bdec_p; d0.C = out; d0.M = NP;
    d1.segs.A[0] = rech_d; d1.segs.B[0] = wdecd;      d1.segs.ldb[0] = 2 * FD;
    d1.segs.A[1] = xnh_d;  d1.segs.B[1] = wdecd + FD; d1.segs.ldb[1] = 2 * FD;
    d1.nseg = 2; d1.bias = bdec_d; d1.C = out + (size_t)NP * FD; d1.M = ND;
    gemm_h<<<ggrid, NTHR, GEMM_SMEM>>>(d0, d1, gp);
}

// round 16
// speedup vs baseline: 1.2779x; 1.0412x over previous
#include <cuda_runtime.h>
#include <cuda_fp16.h>
#include <math.h>
#include <stdint.h>

#define NP 50000
#define ND 5000
#define FD 512

// ---------------------------------------------------------------------------
// Scratch (u32 units)
// ---------------------------------------------------------------------------
constexpr size_t NPF   = (size_t)NP * FD;
constexpr size_t NDF   = (size_t)ND * FD;
constexpr size_t U_SUM_PP = 0;
constexpr size_t U_SUM_DP = U_SUM_PP + NPF;
constexpr size_t U_SUM_PD = U_SUM_DP + NPF;
constexpr size_t U_CNT_PP = U_SUM_PD + NDF;
constexpr size_t U_CNT_DP = U_CNT_PP + NP;
constexpr size_t U_CNT_PD = U_CNT_DP + NP;
constexpr size_t ZERO_END = U_CNT_PD + ND;
constexpr size_t U_MH_PP  = (ZERO_END + 1) & ~(size_t)1;
constexpr size_t U_MH_DP  = U_MH_PP + NPF / 2;
constexpr size_t U_MH_PD  = U_MH_DP + NPF / 2;
constexpr size_t U_XH_P   = U_MH_PD + NDF / 2;     // half x (plain)
constexpr size_t U_XH_D   = U_XH_P + NPF / 2;
constexpr size_t U_XNH_P  = U_XH_D + NDF / 2;      // half x (normalized)
constexpr size_t U_XNH_D  = U_XNH_P + NPF / 2;
constexpr size_t U_RECH_P = U_XNH_D + NDF / 2;     // half rec (normalized)
constexpr size_t U_RECH_D = U_RECH_P + NPF / 2;
constexpr size_t U_WCOMB  = U_RECH_D + NDF / 2;
constexpr size_t U_WRPP   = U_WCOMB + (size_t)FD * FD / 2;
constexpr size_t U_WRDP   = U_WRPP + (size_t)FD * FD / 2;
constexpr size_t U_WRPD   = U_WRDP + (size_t)FD * FD / 2;
constexpr size_t U_WLPD   = U_WRPD + (size_t)FD * FD / 2;
constexpr size_t U_WDECP  = U_WLPD + (size_t)FD * FD / 2;
constexpr size_t U_WDECD  = U_WDECP + (size_t)FD * FD;
constexpr size_t U_BSUM   = U_WDECD + (size_t)FD * FD;
constexpr size_t U_TOTAL  = U_BSUM + FD;

__device__ __align__(16) unsigned g_scratch[U_TOTAL];

__device__ __forceinline__ unsigned pack_h2(float a, float b) {
    __half2 h = __floats2half2_rn(a, b);
    return *reinterpret_cast<unsigned*>(&h);
}

// ---------------------------------------------------------------------------
// k1: zero sums+counts
// ---------------------------------------------------------------------------
__global__ void zero_k(float4* p, size_t n4) {
    size_t i = (size_t)blockIdx.x * blockDim.x + threadIdx.x;
    size_t stride = (size_t)gridDim.x * blockDim.x;
    for (; i < n4; i += stride) p[i] = make_float4(0.f, 0.f, 0.f, 0.f);
}

// ---------------------------------------------------------------------------
// k2: weight prep (half) + bias sum
// ---------------------------------------------------------------------------
struct WArgs {
    const float *wlpp, *wldp, *wrpp, *wrdp, *wrpd, *wlpd, *wdecp, *wdecd, *bpp, *bdp;
    unsigned *o_wcomb, *o_wrpp, *o_wrdp, *o_wrpd, *o_wlpd, *o_wdecp, *o_wdecd;
    float* o_bsum;
};

__global__ void wprep_k(WArgs a) {
    int idx = blockIdx.x * blockDim.x + threadIdx.x;
    const int nh = FD * FD / 2;
    if (idx < nh) {
        int j = 2 * idx;
        a.o_wcomb[idx] = pack_h2(a.wlpp[j] + a.wldp[j], a.wlpp[j + 1] + a.wldp[j + 1]);
        a.o_wrpp[idx]  = pack_h2(a.wrpp[j], a.wrpp[j + 1]);
        a.o_wrdp[idx]  = pack_h2(a.wrdp[j], a.wrdp[j + 1]);
        a.o_wrpd[idx]  = pack_h2(a.wrpd[j], a.wrpd[j + 1]);
        a.o_wlpd[idx]  = pack_h2(a.wlpd[j], a.wlpd[j + 1]);
    }
    if (idx < 2 * nh) {
        int j = 2 * idx;
        a.o_wdecp[idx] = pack_h2(a.wdecp[j], a.wdecp[j + 1]);
        a.o_wdecd[idx] = pack_h2(a.wdecd[j], a.wdecd[j + 1]);
    }
    if (idx < FD) a.o_bsum[idx] = a.bpp[idx] + a.bdp[idx];
}

// ---------------------------------------------------------------------------
// k3: x -> half (plain + l2-normalized), warp per row
// ---------------------------------------------------------------------------
struct XArgs {
    const float* xin[2];
    uint2* xout_p[2];
    uint2* xout_n[2];
    int xrows[2];
};

__global__ void xnorm_k(XArgs a) {
    int row = (int)(((size_t)blockIdx.x * blockDim.x + threadIdx.x) >> 5);
    int t = 0;
    if (row >= a.xrows[0]) { row -= a.xrows[0]; t = 1; }
    if (t == 1 && row >= a.xrows[1]) return;
    int lane = threadIdx.x & 31;
    const float4* p = (const float4*)(a.xin[t] + (size_t)row * FD);
    float4 v[4];
    float ss = 0.f;
#pragma unroll
    for (int i = 0; i < 4; i++) {
        v[i] = p[lane + 32 * i];
        ss += v[i].x * v[i].x + v[i].y * v[i].y + v[i].z * v[i].z + v[i].w * v[i].w;
    }
#pragma unroll
    for (int o = 16; o > 0; o >>= 1) ss += __shfl_xor_sync(0xffffffffu, ss, o);
    float inv = 1.0f / fmaxf(sqrtf(ss), 1e-12f);
    uint2* qp = a.xout_p[t] + (size_t)row * 128;
    uint2* qn = a.xout_n[t] + (size_t)row * 128;
#pragma unroll
    for (int i = 0; i < 4; i++) {
        qp[lane + 32 * i] = make_uint2(pack_h2(v[i].x, v[i].y),
                                       pack_h2(v[i].z, v[i].w));
        qn[lane + 32 * i] = make_uint2(pack_h2(v[i].x * inv, v[i].y * inv),
                                       pack_h2(v[i].z * inv, v[i].w * inv));
    }
}

// ---------------------------------------------------------------------------
// k4: scatter — 64 lanes/group, 4 groups/block, 8 edges batched per group
// (MLP=8 on gathers). Gather half x, fp32 red.
// ---------------------------------------------------------------------------
#define EB 8

struct ScatArgs {
    const int* ei[3];
    const __half* x[3];
    float* sum[3];
    float* cnt[3];
    int E[3];
    int b0, b01;
};

__global__ void scatter_all(ScatArgs a) {
    int b = blockIdx.x, t;
    if (b < a.b0)       { t = 0; }
    else if (b < a.b01) { t = 1; b -= a.b0; }
    else                { t = 2; b -= a.b01; }
    const int grp  = threadIdx.x >> 6;       // 0..3
    const int lane = threadIdx.x & 63;
    const int E = a.E[t];
    const int e0 = (b * 4 + grp) * EB;
    if (e0 >= E) return;
    const int* ei = a.ei[t];
    const __half* x = a.x[t];

    int src[EB], dst[EB];
    bool ok[EB];
#pragma unroll
    for (int i = 0; i < EB; i++) {
        int e = e0 + i;
        ok[i] = e < E;
        src[i] = ok[i] ? ei[e] : 0;
        dst[i] = ok[i] ? ei[(size_t)E + e] : 0;
    }
    uint4 hv[EB];
#pragma unroll
    for (int i = 0; i < EB; i++)
        hv[i] = *(const uint4*)(x + (size_t)src[i] * FD + lane * 8);

#pragma unroll
    for (int i = 0; i < EB; i++) {
        if (!ok[i]) continue;
        float2 f0 = __half22float2(*(__half2*)&hv[i].x);
        float2 f1 = __half22float2(*(__half2*)&hv[i].y);
        float2 f2 = __half22float2(*(__half2*)&hv[i].z);
        float2 f3 = __half22float2(*(__half2*)&hv[i].w);
        float* o = a.sum[t] + (size_t)dst[i] * FD + lane * 8;
        asm volatile("red.global.add.v4.f32 [%0], {%1,%2,%3,%4};"
                     :: "l"(o), "f"(f0.x), "f"(f0.y), "f"(f1.x), "f"(f1.y) : "memory");
        asm volatile("red.global.add.v4.f32 [%0], {%1,%2,%3,%4};"
                     :: "l"(o + 4), "f"(f2.x), "f"(f2.y), "f"(f3.x), "f"(f3.y) : "memory");
        if (lane == 0) atomicAdd(a.cnt[t] + dst[i], 1.0f);
    }
}

// ---------------------------------------------------------------------------
// k5: finalize means -> half, vectorized: 1 uint4 out (8 elems) per thread
// ---------------------------------------------------------------------------
struct FinArgs {
    const float4* sum[3];
    const float* cnt[3];
    uint4* outh[3];
    size_t n[3];       // uint4 jobs per region (= rows * 64)
};

__global__ void finalize_all(FinArgs a) {
    size_t i = (size_t)blockIdx.x * blockDim.x + threadIdx.x;
    int t = 0;
    if (i >= a.n[0]) { i -= a.n[0]; t = 1; }
    if (t == 1 && i >= a.n[1]) { i -= a.n[1]; t = 2; }
    if (t == 2 && i >= a.n[2]) return;
    int row = (int)(i >> 6);                  // 64 uint4 per row
    float iv = 1.0f / fmaxf(a.cnt[t][row], 1.0f);
    const float4* s = a.sum[t] + 2 * i;
    float4 v0 = s[0];
    float4 v1 = s[1];
    a.outh[t][i] = make_uint4(pack_h2(v0.x * iv, v0.y * iv),
                              pack_h2(v0.z * iv, v0.w * iv),
                              pack_h2(v1.x * iv, v1.y * iv),
                              pack_h2(v1.z * iv, v1.w * iv));
}

// ---------------------------------------------------------------------------
// shared GEMM helpers
// ---------------------------------------------------------------------------
struct SegH {
    const __half* A[3];
    const __half* B[3];
    int ldb[3];
};

#define SROW_H 40

__device__ __forceinline__ void cp16s(uint32_t dst_smem, const void* src) {
    asm volatile("cp.async.cg.shared.global [%0], [%1], 16;"
                 :: "r"(dst_smem), "l"(src));
}
__device__ __forceinline__ uint32_t smem_u32(const void* p) {
    uint32_t a;
    asm("{ .reg .u64 t; cvta.to.shared.u64 t, %1; cvt.u32.u64 %0, t; }"
        : "=r"(a) : "l"(p));
    return a;
}
#define LDMX4(r0, r1, r2, r3, addr) \
    asm volatile("ldmatrix.sync.aligned.m8n8.x4.shared.b16 {%0,%1,%2,%3}, [%4];" \
                 : "=r"(r0), "=r"(r1), "=r"(r2), "=r"(r3) : "r"(addr))
#define MMA16816(acc, av, bv) \
    asm volatile( \
        "mma.sync.aligned.m16n8k16.row.col.f32.f16.f16.f32 " \
        "{%0,%1,%2,%3}, {%4,%5,%6,%7}, {%8,%9}, {%0,%1,%2,%3};" \
        : "+f"((acc)[0]), "+f"((acc)[1]), "+f"((acc)[2]), "+f"((acc)[3]) \
        : "r"((av)[0]), "r"((av)[1]), "r"((av)[2]), "r"((av)[3]), \
          "r"((bv)[0]), "r"((bv)[1]))

extern __shared__ __align__(128) unsigned char hsm[];

// ---------------------------------------------------------------------------
// Encoder GEMM: BM=64 x BN=512(full) x BK=32, 256 thr / 8 warps (1x8),
// warp tile 64x64, 4-stage cp.async.
// Epilogue: +bias, full-row L2 norm, write half normalized.
// ---------------------------------------------------------------------------
struct ProbE {
    SegH segs;
    int nseg;
    const float* bias;
    __half* Ch;
    int M;
};

#define E_ASTG (64 * SROW_H * 2)          // 5120
#define E_BSTG (512 * SROW_H * 2)         // 40960
#define E_STG  (E_ASTG + E_BSTG)          // 46080
#define E_SMEM (4 * E_STG)                // 184320

__global__ __launch_bounds__(256, 1) void gemm_enc(ProbE p0, ProbE p1, int split) {
    const bool first = (blockIdx.x < (unsigned)split);
    ProbE p = first ? p0 : p1;
    const int bm = (first ? blockIdx.x : blockIdx.x - split) * 64;

    const int tid  = threadIdx.x;
    const int lane = tid & 31;
    const int wn   = tid >> 5;           // 0..7
    const int g    = lane >> 2;
    const int t4   = lane & 3;

    const uint32_t dyn = smem_u32(hsm);
    __shared__ float rowss[64];

    const uint32_t aoff =
        (uint32_t)(((lane & 15) * SROW_H + ((lane >> 4) << 3)) * 2);
    const uint32_t boff = E_ASTG +
        (uint32_t)(((wn * 64 + (lane & 7) + (((lane >> 4) & 1) << 3)) * SROW_H +
                    (((lane >> 3) & 1) << 3)) * 2);

    float acc[4][8][4];
#pragma unroll
    for (int mi = 0; mi < 4; mi++)
#pragma unroll
        for (int ni = 0; ni < 8; ni++)
#pragma unroll
            for (int r = 0; r < 4; r++) acc[mi][ni][r] = 0.f;

    const int NKB = p.nseg * (FD / 32);

    auto issue = [&](int kb) {
        const int st   = kb & 3;
        const int s    = kb >> 4;
        const int koff = (kb & 15) * 32;
        const uint32_t abase = dyn + st * E_STG;
        const uint32_t bbase = abase + E_ASTG;
        {   // A: 64 rows x 4 c16 = 256 jobs (1/thread)
            int row = tid >> 2, c16 = tid & 3;
            int r = bm + row;
            if (r < p.M)
                cp16s(abase + (uint32_t)(row * (SROW_H * 2) + c16 * 16),
                      p.segs.A[s] + (size_t)r * FD + koff + c16 * 8);
            else {
                uint32_t d = abase + (uint32_t)(row * (SROW_H * 2) + c16 * 16);
                asm volatile("st.shared.v4.u32 [%0], {%1,%1,%1,%1};"
                             :: "r"(d), "r"(0u));
            }
        }
        const __half* Bb = p.segs.B[s];
        const int ldb = p.segs.ldb[s];
#pragma unroll
        for (int i = 0; i < 8; i++) {    // B: 512 rows x 4 = 2048 jobs (8/thread)
            int u = tid + i * 256;
            int row = u >> 2, c16 = u & 3;
            cp16s(bbase + (uint32_t)(row * (SROW_H * 2) + c16 * 16),
                  Bb + (size_t)row * ldb + koff + c16 * 8);
        }
        asm volatile("cp.async.commit_group;");
    };

    issue(0);
    if (NKB > 1) issue(1);
    if (NKB > 2) issue(2);

    for (int c = 0; c < NKB; c++) {
        const int st = c & 3;
        if (c + 3 < NKB) issue(c + 3);
        const int rem = NKB - 1 - c;
        if (rem >= 3)      asm volatile("cp.async.wait_group 3;");
        else if (rem == 2) asm volatile("cp.async.wait_group 2;");
        else if (rem == 1) asm volatile("cp.async.wait_group 1;");
        else               asm volatile("cp.async.wait_group 0;");
        __syncthreads();

        const uint32_t stBase = dyn + st * E_STG;
#pragma unroll
        for (int ks = 0; ks < 2; ks++) {
            unsigned a[4][4], b[8][2];
#pragma unroll
            for (int mi = 0; mi < 4; mi++)
                LDMX4(a[mi][0], a[mi][1], a[mi][2], a[mi][3],
                      stBase + aoff + (uint32_t)(mi * 16 * SROW_H * 2 + ks * 32));
#pragma unroll
            for (int pi = 0; pi < 4; pi++)
                LDMX4(b[2 * pi][0], b[2 * pi][1], b[2 * pi + 1][0], b[2 * pi + 1][1],
                      stBase + boff + (uint32_t)(pi * 16 * SROW_H * 2 + ks * 32));
#pragma unroll
            for (int mi = 0; mi < 4; mi++)
#pragma unroll
                for (int ni = 0; ni < 8; ni++)
                    MMA16816(acc[mi][ni], a[mi], b[ni]);
        }
        __syncthreads();
    }

    // epilogue: +bias, row ssq over full 512 cols, normalize, write half
    float bb[8][2];
#pragma unroll
    for (int ni = 0; ni < 8; ni++) {
        int c = wn * 64 + ni * 8 + t4 * 2;
        bb[ni][0] = p.bias[c];
        bb[ni][1] = p.bias[c + 1];
    }
    if (tid < 64) rowss[tid] = 0.f;
    __syncthreads();
#pragma unroll
    for (int mi = 0; mi < 4; mi++) {
        float s0 = 0.f, s1 = 0.f;
#pragma unroll
        for (int ni = 0; ni < 8; ni++) {
            float v0 = acc[mi][ni][0] + bb[ni][0];
            float v1 = acc[mi][ni][1] + bb[ni][1];
            float v2 = acc[mi][ni][2] + bb[ni][0];
            float v3 = acc[mi][ni][3] + bb[ni][1];
            acc[mi][ni][0] = v0; acc[mi][ni][1] = v1;
            acc[mi][ni][2] = v2; acc[mi][ni][3] = v3;
            s0 += v0 * v0 + v1 * v1;
            s1 += v2 * v2 + v3 * v3;
        }
        s0 += __shfl_xor_sync(0xffffffffu, s0, 1);
        s0 += __shfl_xor_sync(0xffffffffu, s0, 2);
        s1 += __shfl_xor_sync(0xffffffffu, s1, 1);
        s1 += __shfl_xor_sync(0xffffffffu, s1, 2);
        if (t4 == 0) {
            atomicAdd(&rowss[mi * 16 + g], s0);
            atomicAdd(&rowss[mi * 16 + g + 8], s1);
        }
    }
    __syncthreads();
#pragma unroll
    for (int mi = 0; mi < 4; mi++) {
        const int r0 = mi * 16 + g;
        const int gr0 = bm + r0;
        const float inv0 = 1.0f / fmaxf(sqrtf(rowss[r0]), 1e-12f);
        const float inv1 = 1.0f / fmaxf(sqrtf(rowss[r0 + 8]), 1e-12f);
#pragma unroll
        for (int ni = 0; ni < 8; ni++) {
            const int c = wn * 64 + ni * 8 + t4 * 2;
            if (gr0 < p.M)
                *(unsigned*)(p.Ch + (size_t)gr0 * FD + c) =
                    pack_h2(acc[mi][ni][0] * inv0, acc[mi][ni][1] * inv0);
            if (gr0 + 8 < p.M)
                *(unsigned*)(p.Ch + (size_t)(gr0 + 8) * FD + c) =
                    pack_h2(acc[mi][ni][2] * inv1, acc[mi][ni][3] * inv1);
        }
    }
}

// ---------------------------------------------------------------------------
// Decoder GEMM: 128x256x32, 512 thr / 16 warps, warp 64x32.
// ---------------------------------------------------------------------------
struct ProbH {
    SegH segs;
    int nseg;
    const float* bias;
    float* C;
    int M;
};

#define NTHR 512
#define A_BYTES_H (128 * SROW_H * 2)
#define B_BYTES_H (256 * SROW_H * 2)
#define STG_H (A_BYTES_H + B_BYTES_H)
#define GEMM_SMEM (4 * STG_H)

__global__ __launch_bounds__(NTHR, 1) void gemm_h(ProbH p0, ProbH p1, int split) {
    const bool first = (blockIdx.x < (unsigned)split);
    ProbH p = first ? p0 : p1;
    const int bm = (first ? blockIdx.x : blockIdx.x - split) * 128;
    const int bn = blockIdx.y * 256;

    const int tid  = threadIdx.x;
    const int lane = tid & 31;
    const int warp = tid >> 5;
    const int wm = warp >> 3;
    const int wn = warp & 7;
    const int g  = lane >> 2;
    const int t4 = lane & 3;

    const uint32_t dyn = smem_u32(hsm);

    const uint32_t aoff =
        (uint32_t)(((wm * 64 + (lane & 15)) * SROW_H + ((lane >> 4) << 3)) * 2);
    const uint32_t boff = A_BYTES_H +
        (uint32_t)(((wn * 32 + (lane & 7) + (((lane >> 4) & 1) << 3)) * SROW_H +
                    (((lane >> 3) & 1) << 3)) * 2);

    float acc[4][4][4];
#pragma unroll
    for (int mi = 0; mi < 4; mi++)
#pragma unroll
        for (int ni = 0; ni < 4; ni++)
#pragma unroll
            for (int r = 0; r < 4; r++) acc[mi][ni][r] = 0.f;

    const int NKB = p.nseg * (FD / 32);

    auto issue = [&](int kb) {
        const int st   = kb & 3;
        const int s    = kb >> 4;
        const int koff = (kb & 15) * 32;
        const uint32_t abase = dyn + st * STG_H;
        const uint32_t bbase = abase + A_BYTES_H;
        {
            int row = tid >> 2, c16 = tid & 3;
            int r = bm + row;
            if (r < p.M)
                cp16s(abase + (uint32_t)(row * (SROW_H * 2) + c16 * 16),
                      p.segs.A[s] + (size_t)r * FD + koff + c16 * 8);
            else {
                uint32_t d = abase + (uint32_t)(row * (SROW_H * 2) + c16 * 16);
                asm volatile("st.shared.v4.u32 [%0], {%1,%1,%1,%1};"
                             :: "r"(d), "r"(0u));
            }
        }
        const __half* Bb = p.segs.B[s];
        const int ldb = p.segs.ldb[s];
#pragma unroll
        for (int i = 0; i < 2; i++) {
            int u = tid + i * NTHR;
            int row = u >> 2, c16 = u & 3;
            cp16s(bbase + (uint32_t)(row * (SROW_H * 2) + c16 * 16),
                  Bb + (size_t)(bn + row) * ldb + koff + c16 * 8);
        }
        asm volatile("cp.async.commit_group;");
    };

    issue(0);
    if (NKB > 1) issue(1);
    if (NKB > 2) issue(2);

    for (int c = 0; c < NKB; c++) {
        const int st = c & 3;
        if (c + 3 < NKB) issue(c + 3);
        const int rem = NKB - 1 - c;
        if (rem >= 3)      asm volatile("cp.async.wait_group 3;");
        else if (rem == 2) asm volatile("cp.async.wait_group 2;");
        else if (rem == 1) asm volatile("cp.async.wait_group 1;");
        else               asm volatile("cp.async.wait_group 0;");
        __syncthreads();

        const uint32_t stBase = dyn + st * STG_H;
#pragma unroll
        for (int ks = 0; ks < 2; ks++) {
            unsigned a[4][4], b[4][2];
#pragma unroll
            for (int mi = 0; mi < 4; mi++)
                LDMX4(a[mi][0], a[mi][1], a[mi][2], a[mi][3],
                      stBase + aoff + (uint32_t)(mi * 16 * SROW_H * 2 + ks * 32));
#pragma unroll
            for (int pi = 0; pi < 2; pi++)
                LDMX4(b[2 * pi][0], b[2 * pi][1], b[2 * pi + 1][0], b[2 * pi + 1][1],
                      stBase + boff + (uint32_t)(pi * 16 * SROW_H * 2 + ks * 32));
#pragma unroll
            for (int mi = 0; mi < 4; mi++)
#pragma unroll
                for (int ni = 0; ni < 4; ni++)
                    MMA16816(acc[mi][ni], a[mi], b[ni]);
        }
        __syncthreads();
    }

#pragma unroll
    for (int ni = 0; ni < 4; ni++) {
        const int c = bn + wn * 32 + ni * 8 + t4 * 2;
        const float bb0 = p.bias[c];
        const float bb1 = p.bias[c + 1];
#pragma unroll
        for (int mi = 0; mi < 4; mi++) {
            const int r0 = bm + wm * 64 + mi * 16 + g;
            if (r0 < p.M)
                *(float2*)(p.C + (size_t)r0 * FD + c) =
                    make_float2(acc[mi][ni][0] + bb0, acc[mi][ni][1] + bb1);
            const int r1 = r0 + 8;
            if (r1 < p.M)
                *(float2*)(p.C + (size_t)r1 * FD + c) =
                    make_float2(acc[mi][ni][2] + bb0, acc[mi][ni][3] + bb1);
        }
    }
}

// ---------------------------------------------------------------------------
// kernel_launch — 7 launches; #4 = scatter (ncu lands there)
// ---------------------------------------------------------------------------
extern "C" void kernel_launch(void* const* d_in, const int* in_sizes, int n_in,
                              void* d_out, int out_size) {
    const float* x_paper   = (const float*)d_in[0];
    const float* x_dataset = (const float*)d_in[1];
    const int*   ei_pp     = (const int*)d_in[2];
    const int*   ei_pd     = (const int*)d_in[3];
    const int*   ei_dp     = (const int*)d_in[4];
    const float* Wl_pp = (const float*)d_in[5];
    const float* Wr_pp = (const float*)d_in[6];
    const float* b_pp  = (const float*)d_in[7];
    const float* Wl_pd = (const float*)d_in[8];
    const float* Wr_pd = (const float*)d_in[9];
    const float* b_pd  = (const float*)d_in[10];
    const float* Wl_dp = (const float*)d_in[11];
    const float* Wr_dp = (const float*)d_in[12];
    const float* b_dp  = (const float*)d_in[13];
    const float* Wdec_p = (const float*)d_in[14];
    const float* bdec_p = (const float*)d_in[15];
    const float* Wdec_d = (const float*)d_in[16];
    const float* bdec_d = (const float*)d_in[17];

    const int Epp = in_sizes[2] / 2;
    const int Epd = in_sizes[3] / 2;
    const int Edp = in_sizes[4] / 2;

    float* out = (float*)d_out;

    unsigned* base = nullptr;
    cudaGetSymbolAddress((void**)&base, g_scratch);
    float*    sum_pp = (float*)(base + U_SUM_PP);
    float*    sum_dp = (float*)(base + U_SUM_DP);
    float*    sum_pd = (float*)(base + U_SUM_PD);
    float*    cnt_pp = (float*)(base + U_CNT_PP);
    float*    cnt_dp = (float*)(base + U_CNT_DP);
    float*    cnt_pd = (float*)(base + U_CNT_PD);
    __half*   mh_pp  = (__half*)(base + U_MH_PP);
    __half*   mh_dp  = (__half*)(base + U_MH_DP);
    __half*   mh_pd  = (__half*)(base + U_MH_PD);
    __half*   xh_p   = (__half*)(base + U_XH_P);
    __half*   xh_d   = (__half*)(base + U_XH_D);
    __half*   xnh_p  = (__half*)(base + U_XNH_P);
    __half*   xnh_d  = (__half*)(base + U_XNH_D);
    __half*   rech_p = (__half*)(base + U_RECH_P);
    __half*   rech_d = (__half*)(base + U_RECH_D);
    __half*   wcomb  = (__half*)(base + U_WCOMB);
    __half*   wrpp   = (__half*)(base + U_WRPP);
    __half*   wrdp   = (__half*)(base + U_WRDP);
    __half*   wrpd   = (__half*)(base + U_WRPD);
    __half*   wlpd   = (__half*)(base + U_WLPD);
    __half*   wdecp  = (__half*)(base + U_WDECP);
    __half*   wdecd  = (__half*)(base + U_WDECD);
    float*    bsum   = (float*)(base + U_BSUM);

    cudaFuncSetAttribute(gemm_enc, cudaFuncAttributeMaxDynamicSharedMemorySize,
                         E_SMEM);
    cudaFuncSetAttribute(gemm_h, cudaFuncAttributeMaxDynamicSharedMemorySize,
                         GEMM_SMEM);

    // k1: zero sums + counts
    zero_k<<<4096, 256>>>((float4*)base, ZERO_END / 4);

    // k2: weight prep
    WArgs wa;
    wa.wlpp = Wl_pp; wa.wldp = Wl_dp; wa.wrpp = Wr_pp; wa.wrdp = Wr_dp;
    wa.wrpd = Wr_pd; wa.wlpd = Wl_pd; wa.wdecp = Wdec_p; wa.wdecd = Wdec_d;
    wa.bpp = b_pp; wa.bdp = b_dp;
    wa.o_wcomb = (unsigned*)wcomb; wa.o_wrpp = (unsigned*)wrpp;
    wa.o_wrdp = (unsigned*)wrdp; wa.o_wrpd = (unsigned*)wrpd;
    wa.o_wlpd = (unsigned*)wlpd; wa.o_wdecp = (unsigned*)wdecp;
    wa.o_wdecd = (unsigned*)wdecd; wa.o_bsum = bsum;
    wprep_k<<<(FD * FD + 255) / 256, 256>>>(wa);

    // k3: x -> half (plain + normalized)
    XArgs xa;
    xa.xin[0] = x_paper;   xa.xout_p[0] = (uint2*)xh_p; xa.xout_n[0] = (uint2*)xnh_p; xa.xrows[0] = NP;
    xa.xin[1] = x_dataset; xa.xout_p[1] = (uint2*)xh_d; xa.xout_n[1] = (uint2*)xnh_d; xa.xrows[1] = ND;
    xnorm_k<<<((NP + ND) * 32 + 255) / 256, 256>>>(xa);

    // k4: scatter (batched, MLP=8) — ncu profile target
    ScatArgs sa;
    sa.ei[0] = ei_pp; sa.x[0] = xh_p; sa.sum[0] = sum_pp; sa.cnt[0] = cnt_pp; sa.E[0] = Epp;
    sa.ei[1] = ei_dp; sa.x[1] = xh_d; sa.sum[1] = sum_dp; sa.cnt[1] = cnt_dp; sa.E[1] = Edp;
    sa.ei[2] = ei_pd; sa.x[2] = xh_p; sa.sum[2] = sum_pd; sa.cnt[2] = cnt_pd; sa.E[2] = Epd;
    int per = 4 * EB;
    int nb0 = (Epp + per - 1) / per, nb1 = (Edp + per - 1) / per, nb2 = (Epd + per - 1) / per;
    sa.b0 = nb0; sa.b01 = nb0 + nb1;
    scatter_all<<<nb0 + nb1 + nb2, 256>>>(sa);

    // k5: finalize means -> half (vectorized)
    FinArgs fa;
    fa.sum[0] = (const float4*)sum_pp; fa.cnt[0] = cnt_pp; fa.outh[0] = (uint4*)mh_pp; fa.n[0] = (size_t)NP * 64;
    fa.sum[1] = (const float4*)sum_dp; fa.cnt[1] = cnt_dp; fa.outh[1] = (uint4*)mh_dp; fa.n[1] = (size_t)NP * 64;
    fa.sum[2] = (const float4*)sum_pd; fa.cnt[2] = cnt_pd; fa.outh[2] = (uint4*)mh_pd; fa.n[2] = (size_t)ND * 64;
    size_t ftot = fa.n[0] + fa.n[1] + fa.n[2];
    finalize_all<<<(int)((ftot + 255) / 256), 256>>>(fa);

    // k6: encoder GEMMs, fused L2-norm epilogue -> rech (half)
    const int gpe = (NP + 63) / 64;   // 782
    const int gde = (ND + 63) / 64;   // 79
    ProbE e0 = {}, e1 = {};
    e0.segs.A[0] = mh_pp; e0.segs.B[0] = wrpp;  e0.segs.ldb[0] = FD;
    e0.segs.A[1] = mh_dp; e0.segs.B[1] = wrdp;  e0.segs.ldb[1] = FD;
    e0.segs.A[2] = xh_p;  e0.segs.B[2] = wcomb; e0.segs.ldb[2] = FD;
    e0.nseg = 3; e0.bias = bsum; e0.Ch = rech_p; e0.M = NP;
    e1.segs.A[0] = mh_pd; e1.segs.B[0] = wrpd; e1.segs.ldb[0] = FD;
    e1.segs.A[1] = xh_d;  e1.segs.B[1] = wlpd; e1.segs.ldb[1] = FD;
    e1.nseg = 2; e1.bias = b_pd; e1.Ch = rech_d; e1.M = ND;
    gemm_enc<<<gpe + gde, 256, E_SMEM>>>(e0, e1, gpe);

    // k7: decoder GEMMs -> out (fp32)
    const int gp = (NP + 127) / 128;
    const int gd = (ND + 127) / 128;
    dim3 ggrid(gp + gd, FD / 256);
    ProbH d0 = {}, d1 = {};
    d0.segs.A[0] = rech_p; d0.segs.B[0] = wdecp;      d0.segs.ldb[0] = 2 * FD;
    d0.segs.A[1] = xnh_p;  d0.segs.B[1] = wdecp + FD; d0.segs.ldb[1] = 2 * FD;
    d0.nseg = 2; d0.bias = bdec_p; d0.C = out; d0.M = NP;
    d1.segs.A[0] = rech_d; d1.segs.B[0] = wdecd;      d1.segs.ldb[0] = 2 * FD;
    d1.segs.A[1] = xnh_d;  d1.segs.B[1] = wdecd + FD; d1.segs.ldb[1] = 2 * FD;
    d1.nseg = 2; d1.bias = bdec_d; d1.C = out + (size_t)NP * FD; d1.M = ND;
    gemm_h<<<ggrid, NTHR, GEMM_SMEM>>>(d0, d1, gp);
}

// round 17
// speedup vs baseline: 1.2895x; 1.0090x over previous
#include <cuda_runtime.h>
#include <cuda_fp16.h>
#include <math.h>
#include <stdint.h>

#define NP 50000
#define ND 5000
#define FD 512

// ---------------------------------------------------------------------------
// Scratch (u32 units)
// ---------------------------------------------------------------------------
constexpr size_t NPF   = (size_t)NP * FD;
constexpr size_t NDF   = (size_t)ND * FD;
constexpr size_t U_SUM_PP = 0;
constexpr size_t U_SUM_DP = U_SUM_PP + NPF;
constexpr size_t U_SUM_PD = U_SUM_DP + NPF;
constexpr size_t U_CNT_PP = U_SUM_PD + NDF;
constexpr size_t U_CNT_DP = U_CNT_PP + NP;
constexpr size_t U_CNT_PD = U_CNT_DP + NP;
constexpr size_t ZERO_END = U_CNT_PD + ND;
constexpr size_t U_MH_PP  = (ZERO_END + 1) & ~(size_t)1;
constexpr size_t U_MH_DP  = U_MH_PP + NPF / 2;
constexpr size_t U_MH_PD  = U_MH_DP + NPF / 2;
constexpr size_t U_XH_P   = U_MH_PD + NDF / 2;     // half x (plain)
constexpr size_t U_XH_D   = U_XH_P + NPF / 2;
constexpr size_t U_XNH_P  = U_XH_D + NDF / 2;      // half x (normalized)
constexpr size_t U_XNH_D  = U_XNH_P + NPF / 2;
constexpr size_t U_RECH_P = U_XNH_D + NDF / 2;     // half rec (normalized)
constexpr size_t U_RECH_D = U_RECH_P + NPF / 2;
constexpr size_t U_WCOMB  = U_RECH_D + NDF / 2;
constexpr size_t U_WRPP   = U_WCOMB + (size_t)FD * FD / 2;
constexpr size_t U_WRDP   = U_WRPP + (size_t)FD * FD / 2;
constexpr size_t U_WRPD   = U_WRDP + (size_t)FD * FD / 2;
constexpr size_t U_WLPD   = U_WRPD + (size_t)FD * FD / 2;
constexpr size_t U_WDECP  = U_WLPD + (size_t)FD * FD / 2;
constexpr size_t U_WDECD  = U_WDECP + (size_t)FD * FD;
constexpr size_t U_BSUM   = U_WDECD + (size_t)FD * FD;
constexpr size_t U_TOTAL  = U_BSUM + FD;

__device__ __align__(16) unsigned g_scratch[U_TOTAL];

__device__ __forceinline__ unsigned pack_h2(float a, float b) {
    __half2 h = __floats2half2_rn(a, b);
    return *reinterpret_cast<unsigned*>(&h);
}

// ---------------------------------------------------------------------------
// k1: zero sums+counts
// ---------------------------------------------------------------------------
__global__ void zero_k(float4* p, size_t n4) {
    size_t i = (size_t)blockIdx.x * blockDim.x + threadIdx.x;
    size_t stride = (size_t)gridDim.x * blockDim.x;
    for (; i < n4; i += stride) p[i] = make_float4(0.f, 0.f, 0.f, 0.f);
}

// ---------------------------------------------------------------------------
// k2: weight prep (half) + bias sum
// ---------------------------------------------------------------------------
struct WArgs {
    const float *wlpp, *wldp, *wrpp, *wrdp, *wrpd, *wlpd, *wdecp, *wdecd, *bpp, *bdp;
    unsigned *o_wcomb, *o_wrpp, *o_wrdp, *o_wrpd, *o_wlpd, *o_wdecp, *o_wdecd;
    float* o_bsum;
};

__global__ void wprep_k(WArgs a) {
    int idx = blockIdx.x * blockDim.x + threadIdx.x;
    const int nh = FD * FD / 2;
    if (idx < nh) {
        int j = 2 * idx;
        a.o_wcomb[idx] = pack_h2(a.wlpp[j] + a.wldp[j], a.wlpp[j + 1] + a.wldp[j + 1]);
        a.o_wrpp[idx]  = pack_h2(a.wrpp[j], a.wrpp[j + 1]);
        a.o_wrdp[idx]  = pack_h2(a.wrdp[j], a.wrdp[j + 1]);
        a.o_wrpd[idx]  = pack_h2(a.wrpd[j], a.wrpd[j + 1]);
        a.o_wlpd[idx]  = pack_h2(a.wlpd[j], a.wlpd[j + 1]);
    }
    if (idx < 2 * nh) {
        int j = 2 * idx;
        a.o_wdecp[idx] = pack_h2(a.wdecp[j], a.wdecp[j + 1]);
        a.o_wdecd[idx] = pack_h2(a.wdecd[j], a.wdecd[j + 1]);
    }
    if (idx < FD) a.o_bsum[idx] = a.bpp[idx] + a.bdp[idx];
}

// ---------------------------------------------------------------------------
// k3: x -> half (plain + l2-normalized), warp per row
// ---------------------------------------------------------------------------
struct XArgs {
    const float* xin[2];
    uint2* xout_p[2];
    uint2* xout_n[2];
    int xrows[2];
};

__global__ void xnorm_k(XArgs a) {
    int row = (int)(((size_t)blockIdx.x * blockDim.x + threadIdx.x) >> 5);
    int t = 0;
    if (row >= a.xrows[0]) { row -= a.xrows[0]; t = 1; }
    if (t == 1 && row >= a.xrows[1]) return;
    int lane = threadIdx.x & 31;
    const float4* p = (const float4*)(a.xin[t] + (size_t)row * FD);
    float4 v[4];
    float ss = 0.f;
#pragma unroll
    for (int i = 0; i < 4; i++) {
        v[i] = p[lane + 32 * i];
        ss += v[i].x * v[i].x + v[i].y * v[i].y + v[i].z * v[i].z + v[i].w * v[i].w;
    }
#pragma unroll
    for (int o = 16; o > 0; o >>= 1) ss += __shfl_xor_sync(0xffffffffu, ss, o);
    float inv = 1.0f / fmaxf(sqrtf(ss), 1e-12f);
    uint2* qp = a.xout_p[t] + (size_t)row * 128;
    uint2* qn = a.xout_n[t] + (size_t)row * 128;
#pragma unroll
    for (int i = 0; i < 4; i++) {
        qp[lane + 32 * i] = make_uint2(pack_h2(v[i].x, v[i].y),
                                       pack_h2(v[i].z, v[i].w));
        qn[lane + 32 * i] = make_uint2(pack_h2(v[i].x * inv, v[i].y * inv),
                                       pack_h2(v[i].z * inv, v[i].w * inv));
    }
}

// ---------------------------------------------------------------------------
// k4: scatter — 64 lanes/group, 4 groups/block, 16 edges batched per group
// (MLP=16 on gathers). Gather half x, fp32 red.
// ---------------------------------------------------------------------------
#define EB 16

struct ScatArgs {
    const int* ei[3];
    const __half* x[3];
    float* sum[3];
    float* cnt[3];
    int E[3];
    int b0, b01;
};

__global__ void scatter_all(ScatArgs a) {
    int b = blockIdx.x, t;
    if (b < a.b0)       { t = 0; }
    else if (b < a.b01) { t = 1; b -= a.b0; }
    else                { t = 2; b -= a.b01; }
    const int grp  = threadIdx.x >> 6;       // 0..3
    const int lane = threadIdx.x & 63;
    const int E = a.E[t];
    const int e0 = (b * 4 + grp) * EB;
    if (e0 >= E) return;
    const int* ei = a.ei[t];
    const __half* x = a.x[t];

    int src[EB], dst[EB];
    bool ok[EB];
#pragma unroll
    for (int i = 0; i < EB; i++) {
        int e = e0 + i;
        ok[i] = e < E;
        src[i] = ok[i] ? ei[e] : 0;
        dst[i] = ok[i] ? ei[(size_t)E + e] : 0;
    }
    uint4 hv[EB];
#pragma unroll
    for (int i = 0; i < EB; i++)
        hv[i] = *(const uint4*)(x + (size_t)src[i] * FD + lane * 8);

#pragma unroll
    for (int i = 0; i < EB; i++) {
        if (!ok[i]) continue;
        float2 f0 = __half22float2(*(__half2*)&hv[i].x);
        float2 f1 = __half22float2(*(__half2*)&hv[i].y);
        float2 f2 = __half22float2(*(__half2*)&hv[i].z);
        float2 f3 = __half22float2(*(__half2*)&hv[i].w);
        float* o = a.sum[t] + (size_t)dst[i] * FD + lane * 8;
        asm volatile("red.global.add.v4.f32 [%0], {%1,%2,%3,%4};"
                     :: "l"(o), "f"(f0.x), "f"(f0.y), "f"(f1.x), "f"(f1.y) : "memory");
        asm volatile("red.global.add.v4.f32 [%0], {%1,%2,%3,%4};"
                     :: "l"(o + 4), "f"(f2.x), "f"(f2.y), "f"(f3.x), "f"(f3.y) : "memory");
        if (lane == 0) atomicAdd(a.cnt[t] + dst[i], 1.0f);
    }
}

// ---------------------------------------------------------------------------
// k5: finalize means -> half, vectorized: 1 uint4 out (8 elems) per thread
// ---------------------------------------------------------------------------
struct FinArgs {
    const float4* sum[3];
    const float* cnt[3];
    uint4* outh[3];
    size_t n[3];       // uint4 jobs per region (= rows * 64)
};

__global__ void finalize_all(FinArgs a) {
    size_t i = (size_t)blockIdx.x * blockDim.x + threadIdx.x;
    int t = 0;
    if (i >= a.n[0]) { i -= a.n[0]; t = 1; }
    if (t == 1 && i >= a.n[1]) { i -= a.n[1]; t = 2; }
    if (t == 2 && i >= a.n[2]) return;
    int row = (int)(i >> 6);                  // 64 uint4 per row
    float iv = 1.0f / fmaxf(a.cnt[t][row], 1.0f);
    const float4* s = a.sum[t] + 2 * i;
    float4 v0 = s[0];
    float4 v1 = s[1];
    a.outh[t][i] = make_uint4(pack_h2(v0.x * iv, v0.y * iv),
                              pack_h2(v0.z * iv, v0.w * iv),
                              pack_h2(v1.x * iv, v1.y * iv),
                              pack_h2(v1.z * iv, v1.w * iv));
}

// ---------------------------------------------------------------------------
// shared GEMM helpers
// ---------------------------------------------------------------------------
struct SegH {
    const __half* A[3];
    const __half* B[3];
    int ldb[3];
};

#define SROW_H 40

__device__ __forceinline__ void cp16s(uint32_t dst_smem, const void* src) {
    asm volatile("cp.async.cg.shared.global [%0], [%1], 16;"
                 :: "r"(dst_smem), "l"(src));
}
__device__ __forceinline__ uint32_t smem_u32(const void* p) {
    uint32_t a;
    asm("{ .reg .u64 t; cvta.to.shared.u64 t, %1; cvt.u32.u64 %0, t; }"
        : "=r"(a) : "l"(p));
    return a;
}
#define LDMX4(r0, r1, r2, r3, addr) \
    asm volatile("ldmatrix.sync.aligned.m8n8.x4.shared.b16 {%0,%1,%2,%3}, [%4];" \
                 : "=r"(r0), "=r"(r1), "=r"(r2), "=r"(r3) : "r"(addr))
#define MMA16816(acc, av, bv) \
    asm volatile( \
        "mma.sync.aligned.m16n8k16.row.col.f32.f16.f16.f32 " \
        "{%0,%1,%2,%3}, {%4,%5,%6,%7}, {%8,%9}, {%0,%1,%2,%3};" \
        : "+f"((acc)[0]), "+f"((acc)[1]), "+f"((acc)[2]), "+f"((acc)[3]) \
        : "r"((av)[0]), "r"((av)[1]), "r"((av)[2]), "r"((av)[3]), \
          "r"((bv)[0]), "r"((bv)[1]))

extern __shared__ __align__(128) unsigned char hsm[];

// ---------------------------------------------------------------------------
// Encoder GEMM: BM=64 x BN=512(full) x BK=32, 256 thr / 8 warps (1x8),
// warp tile 64x64, 4-stage cp.async.
// Epilogue: +bias, full-row L2 norm, write half normalized.
// ---------------------------------------------------------------------------
struct ProbE {
    SegH segs;
    int nseg;
    const float* bias;
    __half* Ch;
    int M;
};

#define E_ASTG (64 * SROW_H * 2)          // 5120
#define E_BSTG (512 * SROW_H * 2)         // 40960
#define E_STG  (E_ASTG + E_BSTG)          // 46080
#define E_SMEM (4 * E_STG)                // 184320

__global__ __launch_bounds__(256, 1) void gemm_enc(ProbE p0, ProbE p1, int split) {
    const bool first = (blockIdx.x < (unsigned)split);
    ProbE p = first ? p0 : p1;
    const int bm = (first ? blockIdx.x : blockIdx.x - split) * 64;

    const int tid  = threadIdx.x;
    const int lane = tid & 31;
    const int wn   = tid >> 5;           // 0..7
    const int g    = lane >> 2;
    const int t4   = lane & 3;

    const uint32_t dyn = smem_u32(hsm);
    __shared__ float rowss[64];

    const uint32_t aoff =
        (uint32_t)(((lane & 15) * SROW_H + ((lane >> 4) << 3)) * 2);
    const uint32_t boff = E_ASTG +
        (uint32_t)(((wn * 64 + (lane & 7) + (((lane >> 4) & 1) << 3)) * SROW_H +
                    (((lane >> 3) & 1) << 3)) * 2);

    float acc[4][8][4];
#pragma unroll
    for (int mi = 0; mi < 4; mi++)
#pragma unroll
        for (int ni = 0; ni < 8; ni++)
#pragma unroll
            for (int r = 0; r < 4; r++) acc[mi][ni][r] = 0.f;

    const int NKB = p.nseg * (FD / 32);

    auto issue = [&](int kb) {
        const int st   = kb & 3;
        const int s    = kb >> 4;
        const int koff = (kb & 15) * 32;
        const uint32_t abase = dyn + st * E_STG;
        const uint32_t bbase = abase + E_ASTG;
        {   // A: 64 rows x 4 c16 = 256 jobs (1/thread)
            int row = tid >> 2, c16 = tid & 3;
            int r = bm + row;
            if (r < p.M)
                cp16s(abase + (uint32_t)(row * (SROW_H * 2) + c16 * 16),
                      p.segs.A[s] + (size_t)r * FD + koff + c16 * 8);
            else {
                uint32_t d = abase + (uint32_t)(row * (SROW_H * 2) + c16 * 16);
                asm volatile("st.shared.v4.u32 [%0], {%1,%1,%1,%1};"
                             :: "r"(d), "r"(0u));
            }
        }
        const __half* Bb = p.segs.B[s];
        const int ldb = p.segs.ldb[s];
#pragma unroll
        for (int i = 0; i < 8; i++) {    // B: 512 rows x 4 = 2048 jobs (8/thread)
            int u = tid + i * 256;
            int row = u >> 2, c16 = u & 3;
            cp16s(bbase + (uint32_t)(row * (SROW_H * 2) + c16 * 16),
                  Bb + (size_t)row * ldb + koff + c16 * 8);
        }
        asm volatile("cp.async.commit_group;");
    };

    issue(0);
    if (NKB > 1) issue(1);
    if (NKB > 2) issue(2);

    for (int c = 0; c < NKB; c++) {
        const int st = c & 3;
        if (c + 3 < NKB) issue(c + 3);
        const int rem = NKB - 1 - c;
        if (rem >= 3)      asm volatile("cp.async.wait_group 3;");
        else if (rem == 2) asm volatile("cp.async.wait_group 2;");
        else if (rem == 1) asm volatile("cp.async.wait_group 1;");
        else               asm volatile("cp.async.wait_group 0;");
        __syncthreads();

        const uint32_t stBase = dyn + st * E_STG;
#pragma unroll
        for (int ks = 0; ks < 2; ks++) {
            unsigned a[4][4], b[8][2];
#pragma unroll
            for (int mi = 0; mi < 4; mi++)
                LDMX4(a[mi][0], a[mi][1], a[mi][2], a[mi][3],
                      stBase + aoff + (uint32_t)(mi * 16 * SROW_H * 2 + ks * 32));
#pragma unroll
            for (int pi = 0; pi < 4; pi++)
                LDMX4(b[2 * pi][0], b[2 * pi][1], b[2 * pi + 1][0], b[2 * pi + 1][1],
                      stBase + boff + (uint32_t)(pi * 16 * SROW_H * 2 + ks * 32));
#pragma unroll
            for (int mi = 0; mi < 4; mi++)
#pragma unroll
                for (int ni = 0; ni < 8; ni++)
                    MMA16816(acc[mi][ni], a[mi], b[ni]);
        }
        __syncthreads();
    }

    // epilogue: +bias, row ssq over full 512 cols, normalize, write half
    float bb[8][2];
#pragma unroll
    for (int ni = 0; ni < 8; ni++) {
        int c = wn * 64 + ni * 8 + t4 * 2;
        bb[ni][0] = p.bias[c];
        bb[ni][1] = p.bias[c + 1];
    }
    if (tid < 64) rowss[tid] = 0.f;
    __syncthreads();
#pragma unroll
    for (int mi = 0; mi < 4; mi++) {
        float s0 = 0.f, s1 = 0.f;
#pragma unroll
        for (int ni = 0; ni < 8; ni++) {
            float v0 = acc[mi][ni][0] + bb[ni][0];
            float v1 = acc[mi][ni][1] + bb[ni][1];
            float v2 = acc[mi][ni][2] + bb[ni][0];
            float v3 = acc[mi][ni][3] + bb[ni][1];
            acc[mi][ni][0] = v0; acc[mi][ni][1] = v1;
            acc[mi][ni][2] = v2; acc[mi][ni][3] = v3;
            s0 += v0 * v0 + v1 * v1;
            s1 += v2 * v2 + v3 * v3;
        }
        s0 += __shfl_xor_sync(0xffffffffu, s0, 1);
        s0 += __shfl_xor_sync(0xffffffffu, s0, 2);
        s1 += __shfl_xor_sync(0xffffffffu, s1, 1);
        s1 += __shfl_xor_sync(0xffffffffu, s1, 2);
        if (t4 == 0) {
            atomicAdd(&rowss[mi * 16 + g], s0);
            atomicAdd(&rowss[mi * 16 + g + 8], s1);
        }
    }
    __syncthreads();
#pragma unroll
    for (int mi = 0; mi < 4; mi++) {
        const int r0 = mi * 16 + g;
        const int gr0 = bm + r0;
        const float inv0 = 1.0f / fmaxf(sqrtf(rowss[r0]), 1e-12f);
        const float inv1 = 1.0f / fmaxf(sqrtf(rowss[r0 + 8]), 1e-12f);
#pragma unroll
        for (int ni = 0; ni < 8; ni++) {
            const int c = wn * 64 + ni * 8 + t4 * 2;
            if (gr0 < p.M)
                *(unsigned*)(p.Ch + (size_t)gr0 * FD + c) =
                    pack_h2(acc[mi][ni][0] * inv0, acc[mi][ni][1] * inv0);
            if (gr0 + 8 < p.M)
                *(unsigned*)(p.Ch + (size_t)(gr0 + 8) * FD + c) =
                    pack_h2(acc[mi][ni][2] * inv1, acc[mi][ni][3] * inv1);
        }
    }
}

// ---------------------------------------------------------------------------
// Decoder GEMM: 128x256x32, 512 thr / 16 warps, warp 64x32.
// ---------------------------------------------------------------------------
struct ProbH {
    SegH segs;
    int nseg;
    const float* bias;
    float* C;
    int M;
};

#define NTHR 512
#define A_BYTES_H (128 * SROW_H * 2)
#define B_BYTES_H (256 * SROW_H * 2)
#define STG_H (A_BYTES_H + B_BYTES_H)
#define GEMM_SMEM (4 * STG_H)

__global__ __launch_bounds__(NTHR, 1) void gemm_h(ProbH p0, ProbH p1, int split) {
    const bool first = (blockIdx.x < (unsigned)split);
    ProbH p = first ? p0 : p1;
    const int bm = (first ? blockIdx.x : blockIdx.x - split) * 128;
    const int bn = blockIdx.y * 256;

    const int tid  = threadIdx.x;
    const int lane = tid & 31;
    const int warp = tid >> 5;
    const int wm = warp >> 3;
    const int wn = warp & 7;
    const int g  = lane >> 2;
    const int t4 = lane & 3;

    const uint32_t dyn = smem_u32(hsm);

    const uint32_t aoff =
        (uint32_t)(((wm * 64 + (lane & 15)) * SROW_H + ((lane >> 4) << 3)) * 2);
    const uint32_t boff = A_BYTES_H +
        (uint32_t)(((wn * 32 + (lane & 7) + (((lane >> 4) & 1) << 3)) * SROW_H +
                    (((lane >> 3) & 1) << 3)) * 2);

    float acc[4][4][4];
#pragma unroll
    for (int mi = 0; mi < 4; mi++)
#pragma unroll
        for (int ni = 0; ni < 4; ni++)
#pragma unroll
            for (int r = 0; r < 4; r++) acc[mi][ni][r] = 0.f;

    const int NKB = p.nseg * (FD / 32);

    auto issue = [&](int kb) {
        const int st   = kb & 3;
        const int s    = kb >> 4;
        const int koff = (kb & 15) * 32;
        const uint32_t abase = dyn + st * STG_H;
        const uint32_t bbase = abase + A_BYTES_H;
        {
            int row = tid >> 2, c16 = tid & 3;
            int r = bm + row;
            if (r < p.M)
                cp16s(abase + (uint32_t)(row * (SROW_H * 2) + c16 * 16),
                      p.segs.A[s] + (size_t)r * FD + koff + c16 * 8);
            else {
                uint32_t d = abase + (uint32_t)(row * (SROW_H * 2) + c16 * 16);
                asm volatile("st.shared.v4.u32 [%0], {%1,%1,%1,%1};"
                             :: "r"(d), "r"(0u));
            }
        }
        const __half* Bb = p.segs.B[s];
        const int ldb = p.segs.ldb[s];
#pragma unroll
        for (int i = 0; i < 2; i++) {
            int u = tid + i * NTHR;
            int row = u >> 2, c16 = u & 3;
            cp16s(bbase + (uint32_t)(row * (SROW_H * 2) + c16 * 16),
                  Bb + (size_t)(bn + row) * ldb + koff + c16 * 8);
        }
        asm volatile("cp.async.commit_group;");
    };

    issue(0);
    if (NKB > 1) issue(1);
    if (NKB > 2) issue(2);

    for (int c = 0; c < NKB; c++) {
        const int st = c & 3;
        if (c + 3 < NKB) issue(c + 3);
        const int rem = NKB - 1 - c;
        if (rem >= 3)      asm volatile("cp.async.wait_group 3;");
        else if (rem == 2) asm volatile("cp.async.wait_group 2;");
        else if (rem == 1) asm volatile("cp.async.wait_group 1;");
        else               asm volatile("cp.async.wait_group 0;");
        __syncthreads();

        const uint32_t stBase = dyn + st * STG_H;
#pragma unroll
        for (int ks = 0; ks < 2; ks++) {
            unsigned a[4][4], b[4][2];
#pragma unroll
            for (int mi = 0; mi < 4; mi++)
                LDMX4(a[mi][0], a[mi][1], a[mi][2], a[mi][3],
                      stBase + aoff + (uint32_t)(mi * 16 * SROW_H * 2 + ks * 32));
#pragma unroll
            for (int pi = 0; pi < 2; pi++)
                LDMX4(b[2 * pi][0], b[2 * pi][1], b[2 * pi + 1][0], b[2 * pi + 1][1],
                      stBase + boff + (uint32_t)(pi * 16 * SROW_H * 2 + ks * 32));
#pragma unroll
            for (int mi = 0; mi < 4; mi++)
#pragma unroll
                for (int ni = 0; ni < 4; ni++)
                    MMA16816(acc[mi][ni], a[mi], b[ni]);
        }
        __syncthreads();
    }

#pragma unroll
    for (int ni = 0; ni < 4; ni++) {
        const int c = bn + wn * 32 + ni * 8 + t4 * 2;
        const float bb0 = p.bias[c];
        const float bb1 = p.bias[c + 1];
#pragma unroll
        for (int mi = 0; mi < 4; mi++) {
            const int r0 = bm + wm * 64 + mi * 16 + g;
            if (r0 < p.M)
                *(float2*)(p.C + (size_t)r0 * FD + c) =
                    make_float2(acc[mi][ni][0] + bb0, acc[mi][ni][1] + bb1);
            const int r1 = r0 + 8;
            if (r1 < p.M)
                *(float2*)(p.C + (size_t)r1 * FD + c) =
                    make_float2(acc[mi][ni][2] + bb0, acc[mi][ni][3] + bb1);
        }
    }
}

// ---------------------------------------------------------------------------
// kernel_launch — 7 launches; #4 = scatter (ncu lands there)
// ---------------------------------------------------------------------------
extern "C" void kernel_launch(void* const* d_in, const int* in_sizes, int n_in,
                              void* d_out, int out_size) {
    const float* x_paper   = (const float*)d_in[0];
    const float* x_dataset = (const float*)d_in[1];
    const int*   ei_pp     = (const int*)d_in[2];
    const int*   ei_pd     = (const int*)d_in[3];
    const int*   ei_dp     = (const int*)d_in[4];
    const float* Wl_pp = (const float*)d_in[5];
    const float* Wr_pp = (const float*)d_in[6];
    const float* b_pp  = (const float*)d_in[7];
    const float* Wl_pd = (const float*)d_in[8];
    const float* Wr_pd = (const float*)d_in[9];
    const float* b_pd  = (const float*)d_in[10];
    const float* Wl_dp = (const float*)d_in[11];
    const float* Wr_dp = (const float*)d_in[12];
    const float* b_dp  = (const float*)d_in[13];
    const float* Wdec_p = (const float*)d_in[14];
    const float* bdec_p = (const float*)d_in[15];
    const float* Wdec_d = (const float*)d_in[16];
    const float* bdec_d = (const float*)d_in[17];

    const int Epp = in_sizes[2] / 2;
    const int Epd = in_sizes[3] / 2;
    const int Edp = in_sizes[4] / 2;

    float* out = (float*)d_out;

    unsigned* base = nullptr;
    cudaGetSymbolAddress((void**)&base, g_scratch);
    float*    sum_pp = (float*)(base + U_SUM_PP);
    float*    sum_dp = (float*)(base + U_SUM_DP);
    float*    sum_pd = (float*)(base + U_SUM_PD);
    float*    cnt_pp = (float*)(base + U_CNT_PP);
    float*    cnt_dp = (float*)(base + U_CNT_DP);
    float*    cnt_pd = (float*)(base + U_CNT_PD);
    __half*   mh_pp  = (__half*)(base + U_MH_PP);
    __half*   mh_dp  = (__half*)(base + U_MH_DP);
    __half*   mh_pd  = (__half*)(base + U_MH_PD);
    __half*   xh_p   = (__half*)(base + U_XH_P);
    __half*   xh_d   = (__half*)(base + U_XH_D);
    __half*   xnh_p  = (__half*)(base + U_XNH_P);
    __half*   xnh_d  = (__half*)(base + U_XNH_D);
    __half*   rech_p = (__half*)(base + U_RECH_P);
    __half*   rech_d = (__half*)(base + U_RECH_D);
    __half*   wcomb  = (__half*)(base + U_WCOMB);
    __half*   wrpp   = (__half*)(base + U_WRPP);
    __half*   wrdp   = (__half*)(base + U_WRDP);
    __half*   wrpd   = (__half*)(base + U_WRPD);
    __half*   wlpd   = (__half*)(base + U_WLPD);
    __half*   wdecp  = (__half*)(base + U_WDECP);
    __half*   wdecd  = (__half*)(base + U_WDECD);
    float*    bsum   = (float*)(base + U_BSUM);

    cudaFuncSetAttribute(gemm_enc, cudaFuncAttributeMaxDynamicSharedMemorySize,
                         E_SMEM);
    cudaFuncSetAttribute(gemm_h, cudaFuncAttributeMaxDynamicSharedMemorySize,
                         GEMM_SMEM);

    // k1: zero sums + counts
    zero_k<<<4096, 256>>>((float4*)base, ZERO_END / 4);

    // k2: weight prep
    WArgs wa;
    wa.wlpp = Wl_pp; wa.wldp = Wl_dp; wa.wrpp = Wr_pp; wa.wrdp = Wr_dp;
    wa.wrpd = Wr_pd; wa.wlpd = Wl_pd; wa.wdecp = Wdec_p; wa.wdecd = Wdec_d;
    wa.bpp = b_pp; wa.bdp = b_dp;
    wa.o_wcomb = (unsigned*)wcomb; wa.o_wrpp = (unsigned*)wrpp;
    wa.o_wrdp = (unsigned*)wrdp; wa.o_wrpd = (unsigned*)wrpd;
    wa.o_wlpd = (unsigned*)wlpd; wa.o_wdecp = (unsigned*)wdecp;
    wa.o_wdecd = (unsigned*)wdecd; wa.o_bsum = bsum;
    wprep_k<<<(FD * FD + 255) / 256, 256>>>(wa);

    // k3: x -> half (plain + normalized)
    XArgs xa;
    xa.xin[0] = x_paper;   xa.xout_p[0] = (uint2*)xh_p; xa.xout_n[0] = (uint2*)xnh_p; xa.xrows[0] = NP;
    xa.xin[1] = x_dataset; xa.xout_p[1] = (uint2*)xh_d; xa.xout_n[1] = (uint2*)xnh_d; xa.xrows[1] = ND;
    xnorm_k<<<((NP + ND) * 32 + 255) / 256, 256>>>(xa);

    // k4: scatter (batched, MLP=16) — ncu profile target
    ScatArgs sa;
    sa.ei[0] = ei_pp; sa.x[0] = xh_p; sa.sum[0] = sum_pp; sa.cnt[0] = cnt_pp; sa.E[0] = Epp;
    sa.ei[1] = ei_dp; sa.x[1] = xh_d; sa.sum[1] = sum_dp; sa.cnt[1] = cnt_dp; sa.E[1] = Edp;
    sa.ei[2] = ei_pd; sa.x[2] = xh_p; sa.sum[2] = sum_pd; sa.cnt[2] = cnt_pd; sa.E[2] = Epd;
    int per = 4 * EB;
    int nb0 = (Epp + per - 1) / per, nb1 = (Edp + per - 1) / per, nb2 = (Epd + per - 1) / per;
    sa.b0 = nb0; sa.b01 = nb0 + nb1;
    scatter_all<<<nb0 + nb1 + nb2, 256>>>(sa);

    // k5: finalize means -> half (vectorized)
    FinArgs fa;
    fa.sum[0] = (const float4*)sum_pp; fa.cnt[0] = cnt_pp; fa.outh[0] = (uint4*)mh_pp; fa.n[0] = (size_t)NP * 64;
    fa.sum[1] = (const float4*)sum_dp; fa.cnt[1] = cnt_dp; fa.outh[1] = (uint4*)mh_dp; fa.n[1] = (size_t)NP * 64;
    fa.sum[2] = (const float4*)sum_pd; fa.cnt[2] = cnt_pd; fa.outh[2] = (uint4*)mh_pd; fa.n[2] = (size_t)ND * 64;
    size_t ftot = fa.n[0] + fa.n[1] + fa.n[2];
    finalize_all<<<(int)((ftot + 255) / 256), 256>>>(fa);

    // k6: encoder GEMMs, fused L2-norm epilogue -> rech (half)
    const int gpe = (NP + 63) / 64;   // 782
    const int gde = (ND + 63) / 64;   // 79
    ProbE e0 = {}, e1 = {};
    e0.segs.A[0] = mh_pp; e0.segs.B[0] = wrpp;  e0.segs.ldb[0] = FD;
    e0.segs.A[1] = mh_dp; e0.segs.B[1] = wrdp;  e0.segs.ldb[1] = FD;
    e0.segs.A[2] = xh_p;  e0.segs.B[2] = wcomb; e0.segs.ldb[2] = FD;
    e0.nseg = 3; e0.bias = bsum; e0.Ch = rech_p; e0.M = NP;
    e1.segs.A[0] = mh_pd; e1.segs.B[0] = wrpd; e1.segs.ldb[0] = FD;
    e1.segs.A[1] = xh_d;  e1.segs.B[1] = wlpd; e1.segs.ldb[1] = FD;
    e1.nseg = 2; e1.bias = b_pd; e1.Ch = rech_d; e1.M = ND;
    gemm_enc<<<gpe + gde, 256, E_SMEM>>>(e0, e1, gpe);

    // k7: decoder GEMMs -> out (fp32)
    const int gp = (NP + 127) / 128;
    const int gd = (ND + 127) / 128;
    dim3 ggrid(gp + gd, FD / 256);
    ProbH d0 = {}, d1 = {};
    d0.segs.A[0] = rech_p; d0.segs.B[0] = wdecp;      d0.segs.ldb[0] = 2 * FD;
    d0.segs.A[1] = xnh_p;  d0.segs.B[1] = wdecp + FD; d0.segs.ldb[1] = 2 * FD;
    d0.nseg = 2; d0.bias = bdec_p; d0.C = out; d0.M = NP;
    d1.segs.A[0] = rech_d; d1.segs.B[0] = wdecd;      d1.segs.ldb[0] = 2 * FD;
    d1.segs.A[1] = xnh_d;  d1.segs.B[1] = wdecd + FD; d1.segs.ldb[1] = 2 * FD;
    d1.nseg = 2; d1.bias = bdec_d; d1.C = out + (size_t)NP * FD; d1.M = ND;
    gemm_h<<<ggrid, NTHR, GEMM_SMEM>>>(d0, d1, gp);
}